// round 13
// baseline (speedup 1.0000x reference)
#include <cuda_runtime.h>
#include <cuda_bf16.h>
#include <math.h>

#define N_NODES 8192
#define E_EDGES 262144
#define IN_CH_  128
#define MP_CH   512
#define HID_    256
#define KCL     10
#define EPSF    0.001f
#define DELTAF  0.311f
#define TV_COEFF 0.785f
#define BAL_COEFF 0.514f

// ---------------- scratch (device globals; no allocation allowed) ----------------
__device__ float          g_bufA[N_NODES * MP_CH];
__device__ float          g_hid [N_NODES * HID_];
__device__ float          g_s   [N_NODES * KCL];
__device__ unsigned       g_bitmap[(N_NODES * (size_t)N_NODES) / 32];   // 8 MB
__device__ int            g_counts[N_NODES];       // cleared by tail kernel each call
__device__ int            g_rowptr[N_NODES + 1];
__device__ int            g_offs  [N_NODES];       // scan writes fresh copy each call
__device__ int2           g_epay  [E_EDGES];       // (src, w_bits) sorted by dst
__device__ int            g_nedges;                // cleared by tail kernel
__device__ int            g_done;                  // cleared by tail kernel
__device__ double         g_tv_part[64];
__device__ double         g_asym_part[80];
__device__ float          g_quant[KCL];
__device__ __nv_bfloat16  g_ah [N_NODES * MP_CH];  // A hi (bf16 split)
__device__ __nv_bfloat16  g_al [N_NODES * MP_CH];  // A lo
__device__ __nv_bfloat16  g_bh1[IN_CH_ * MP_CH];   // W1 split (N x K)
__device__ __nv_bfloat16  g_bl1[IN_CH_ * MP_CH];
__device__ __nv_bfloat16  g_bh2[MP_CH * MP_CH];    // W2 split
__device__ __nv_bfloat16  g_bl2[MP_CH * MP_CH];
__device__ __nv_bfloat16  g_bh3[MP_CH * HID_];     // Wm1 split
__device__ __nv_bfloat16  g_bl3[MP_CH * HID_];

// ---------------- PTX helpers (sm_80-compatible; no arch-gated features) ---------
__device__ __forceinline__ unsigned smem_u32(const void* p) {
    unsigned a;
    asm("{ .reg .u64 t; cvta.to.shared.u64 t, %1; cvt.u32.u64 %0, t; }" : "=r"(a) : "l"(p));
    return a;
}
__device__ __forceinline__ void cp16(unsigned dst, const void* src) {
    asm volatile("cp.async.cg.shared.global [%0], [%1], 16;" :: "r"(dst), "l"(src));
}
__device__ __forceinline__ void cp_commit() {
    asm volatile("cp.async.commit_group;" ::: "memory");
}
__device__ __forceinline__ void cp_wait0() {
    asm volatile("cp.async.wait_group 0;" ::: "memory");
}
__device__ __forceinline__ void cp_wait1() {
    asm volatile("cp.async.wait_group 1;" ::: "memory");
}
__device__ __forceinline__ void ldsm4(unsigned& r0, unsigned& r1, unsigned& r2, unsigned& r3,
                                      unsigned addr) {
    asm volatile("ldmatrix.sync.aligned.m8n8.x4.shared.b16 {%0,%1,%2,%3}, [%4];"
                 : "=r"(r0), "=r"(r1), "=r"(r2), "=r"(r3) : "r"(addr));
}
__device__ __forceinline__ void ldsm2(unsigned& r0, unsigned& r1, unsigned addr) {
    asm volatile("ldmatrix.sync.aligned.m8n8.x2.shared.b16 {%0,%1}, [%2];"
                 : "=r"(r0), "=r"(r1) : "r"(addr));
}
__device__ __forceinline__ void mma16816(float* d, const unsigned* a, const unsigned* b) {
    asm volatile(
        "mma.sync.aligned.m16n8k16.row.col.f32.bf16.bf16.f32 "
        "{%0,%1,%2,%3}, {%4,%5,%6,%7}, {%8,%9}, {%0,%1,%2,%3};"
        : "+f"(d[0]), "+f"(d[1]), "+f"(d[2]), "+f"(d[3])
        : "r"(a[0]), "r"(a[1]), "r"(a[2]), "r"(a[3]), "r"(b[0]), "r"(b[1]));
}

// ---------------- CSR build (by dst) + bitmap spot-clear, x4 ILP ----------------
__global__ void k_hist(const int* __restrict__ src, const int* __restrict__ dst) {
    int t = blockIdx.x * blockDim.x + threadIdx.x;   // grid covers E/4
    int4 s4 = ((const int4*)src)[t];
    int4 d4 = ((const int4*)dst)[t];
    atomicAdd(&g_counts[d4.x], 1);
    atomicAdd(&g_counts[d4.y], 1);
    atomicAdd(&g_counts[d4.z], 1);
    atomicAdd(&g_counts[d4.w], 1);
    g_bitmap[((unsigned)s4.x * N_NODES + (unsigned)d4.x) >> 5] = 0u;
    g_bitmap[((unsigned)s4.y * N_NODES + (unsigned)d4.y) >> 5] = 0u;
    g_bitmap[((unsigned)s4.z * N_NODES + (unsigned)d4.z) >> 5] = 0u;
    g_bitmap[((unsigned)s4.w * N_NODES + (unsigned)d4.w) >> 5] = 0u;
}

__global__ void k_scan() {   // single block, 1024 threads, 8 elems each
    __shared__ int tsum[1024];
    int tid = threadIdx.x;
    int base = tid * 8;
    int local[8];
    int s = 0;
    #pragma unroll
    for (int i = 0; i < 8; i++) { local[i] = s; s += g_counts[base + i]; }
    tsum[tid] = s;
    __syncthreads();
    for (int off = 1; off < 1024; off <<= 1) {
        int v = 0;
        if (tid >= off) v = tsum[tid - off];
        __syncthreads();
        if (tid >= off) tsum[tid] += v;
        __syncthreads();
    }
    int prefix = tsum[tid] - s;
    #pragma unroll
    for (int i = 0; i < 8; i++) {
        int v = prefix + local[i];
        g_rowptr[base + i] = v;
        g_offs[base + i] = v;
    }
    if (tid == 1023) g_rowptr[N_NODES] = tsum[1023];
}

__global__ void k_scatter(const int* __restrict__ src, const int* __restrict__ dst,
                          const float* __restrict__ ew) {
    int t = blockIdx.x * blockDim.x + threadIdx.x;   // grid covers E/4
    int4 s4 = ((const int4*)src)[t];
    int4 d4 = ((const int4*)dst)[t];
    float4 w4 = ((const float4*)ew)[t];
    int p0 = atomicAdd(&g_offs[d4.x], 1);
    g_epay[p0] = make_int2(s4.x, __float_as_int(w4.x));
    int p1 = atomicAdd(&g_offs[d4.y], 1);
    g_epay[p1] = make_int2(s4.y, __float_as_int(w4.y));
    int p2 = atomicAdd(&g_offs[d4.z], 1);
    g_epay[p2] = make_int2(s4.z, __float_as_int(w4.z));
    int p3 = atomicAdd(&g_offs[d4.w], 1);
    g_epay[p3] = make_int2(s4.w, __float_as_int(w4.w));
}

// ---------------- wsplit body (transpose + bf16 split) ----------------
__device__ __forceinline__ void wsplit_body(
    const float* __restrict__ W, __nv_bfloat16* __restrict__ Bh,
    __nv_bfloat16* __restrict__ Bl, int Kdim, int Nn,
    int bx, int by, float (*t)[33])
{
    int tid = threadIdx.x;
    int tx = tid & 31, ty = tid >> 5;   // 32 x 8
    int kb = by * 32, nb = bx * 32;
    #pragma unroll
    for (int i = 0; i < 4; i++)
        t[ty + i * 8][tx] = W[(size_t)(kb + ty + i * 8) * Nn + nb + tx];
    __syncthreads();
    #pragma unroll
    for (int i = 0; i < 4; i++) {
        int nl = ty + i * 8;
        float a = t[tx][nl];
        __nv_bfloat16 hi = __float2bfloat16_rn(a);
        __nv_bfloat16 lo = __float2bfloat16_rn(a - __bfloat162float(hi));
        Bh[(size_t)(nb + nl) * Kdim + kb + tx] = hi;
        Bl[(size_t)(nb + nl) * Kdim + kb + tx] = lo;
    }
}

__global__ void k_wsplit(const float* __restrict__ W,
                         __nv_bfloat16* __restrict__ Bh,
                         __nv_bfloat16* __restrict__ Bl, int Kdim, int Nn) {
    __shared__ float t[32][33];
    wsplit_body(W, Bh, Bl, Kdim, Nn, blockIdx.x, blockIdx.y, t);
}

// ---------------- fused: x split (1024 blocks) + W1 split (64 blocks) ------------
__global__ void k_fsplit(const float* __restrict__ x, const float* __restrict__ W1,
                         __nv_bfloat16* __restrict__ Ah, __nv_bfloat16* __restrict__ Al,
                         __nv_bfloat16* __restrict__ Bh, __nv_bfloat16* __restrict__ Bl) {
    __shared__ float t[32][33];
    int b = blockIdx.x;
    if (b < 1024) {
        int i = b * 256 + threadIdx.x;
        float4 v = ((const float4*)x)[i];
        float f[4] = {v.x, v.y, v.z, v.w};
        __nv_bfloat16 hi[4], lo[4];
        #pragma unroll
        for (int j = 0; j < 4; j++) {
            hi[j] = __float2bfloat16_rn(f[j]);
            lo[j] = __float2bfloat16_rn(f[j] - __bfloat162float(hi[j]));
        }
        __nv_bfloat162* ph = (__nv_bfloat162*)(Ah + i * 4);
        __nv_bfloat162* pl = (__nv_bfloat162*)(Al + i * 4);
        ph[0] = __nv_bfloat162(hi[0], hi[1]);
        ph[1] = __nv_bfloat162(hi[2], hi[3]);
        pl[0] = __nv_bfloat162(lo[0], lo[1]);
        pl[1] = __nv_bfloat162(lo[2], lo[3]);
    } else {
        int bb = b - 1024;
        wsplit_body(W1, Bh, Bl, IN_CH_, MP_CH, bb & 15, bb >> 4, t);
    }
}

// ---------------- HMMA bf16-split GEMM ----------------
#define AH_OFF 0
#define AL_OFF 10240
#define BH_OFF 20480
#define BL_OFF 30720
#define STAGE_BYTES 40960
#define SM_TOTAL (2 * STAGE_BYTES)

__device__ __forceinline__ void load_stage(
    unsigned sbase,
    const __nv_bfloat16* __restrict__ Ah, const __nv_bfloat16* __restrict__ Al,
    const __nv_bfloat16* __restrict__ Bh, const __nv_bfloat16* __restrict__ Bl,
    int m0, int n0, int k0, int Kdim)
{
    int tid = threadIdx.x;
    #pragma unroll
    for (int it = 0; it < 2; it++) {
        int c = it * 256 + tid;
        int row = c >> 2, seg = c & 3;
        unsigned so = row * 80 + seg * 16;
        size_t goa = (size_t)(m0 + row) * Kdim + k0 + seg * 8;
        size_t gob = (size_t)(n0 + row) * Kdim + k0 + seg * 8;
        cp16(sbase + AH_OFF + so, Ah + goa);
        cp16(sbase + AL_OFF + so, Al + goa);
        cp16(sbase + BH_OFF + so, Bh + gob);
        cp16(sbase + BL_OFF + so, Bl + gob);
    }
}

__global__ __launch_bounds__(256) void k_mma(
    const __nv_bfloat16* __restrict__ Ah, const __nv_bfloat16* __restrict__ Al,
    const __nv_bfloat16* __restrict__ Bh, const __nv_bfloat16* __restrict__ Bl,
    const float* __restrict__ bias, float* __restrict__ C,
    int Kdim, int Nn, int relu)
{
    extern __shared__ char smem[];
    unsigned sb = smem_u32(smem);
    int tid = threadIdx.x;
    int wid = tid >> 5, lane = tid & 31;
    int wm = wid >> 2, wn = wid & 3;

    int m0 = blockIdx.y * 128, n0 = blockIdx.x * 128;
    int nch = Kdim >> 5;

    float acc[4][4][4];
    #pragma unroll
    for (int mt = 0; mt < 4; mt++)
        #pragma unroll
        for (int nt = 0; nt < 4; nt++)
            #pragma unroll
            for (int q = 0; q < 4; q++) acc[mt][nt][q] = 0.f;

    load_stage(sb, Ah, Al, Bh, Bl, m0, n0, 0, Kdim);
    cp_commit();

    for (int ch = 0; ch < nch; ch++) {
        unsigned stage = sb + (unsigned)(ch & 1) * STAGE_BYTES;
        if (ch + 1 < nch) {
            load_stage(sb + (unsigned)((ch + 1) & 1) * STAGE_BYTES,
                       Ah, Al, Bh, Bl, m0, n0, (ch + 1) << 5, Kdim);
            cp_commit();
            cp_wait1();
        } else {
            cp_wait0();
        }
        __syncthreads();

        unsigned AsH = stage + AH_OFF, AsL = stage + AL_OFF;
        unsigned BsH = stage + BH_OFF, BsL = stage + BL_OFF;
        #pragma unroll
        for (int k0 = 0; k0 < 32; k0 += 16) {
            unsigned bh[4][2], bl[4][2], ah[4][4], al[4][4];
            int rB = lane & 7, kB = lane & 8;
            #pragma unroll
            for (int nt = 0; nt < 4; nt++) {
                unsigned off = (unsigned)(wn * 32 + nt * 8 + rB) * 80 + (k0 + kB) * 2;
                ldsm2(bh[nt][0], bh[nt][1], BsH + off);
                ldsm2(bl[nt][0], bl[nt][1], BsL + off);
            }
            int rA = lane & 15, kA = (lane >> 4) << 3;
            #pragma unroll
            for (int mt = 0; mt < 4; mt++) {
                unsigned off = (unsigned)(wm * 64 + mt * 16 + rA) * 80 + (k0 + kA) * 2;
                ldsm4(ah[mt][0], ah[mt][1], ah[mt][2], ah[mt][3], AsH + off);
                ldsm4(al[mt][0], al[mt][1], al[mt][2], al[mt][3], AsL + off);
            }
            #pragma unroll
            for (int mt = 0; mt < 4; mt++)
                #pragma unroll
                for (int nt = 0; nt < 4; nt++) {
                    mma16816(acc[mt][nt], ah[mt], bh[nt]);
                    mma16816(acc[mt][nt], ah[mt], bl[nt]);
                    mma16816(acc[mt][nt], al[mt], bh[nt]);
                }
        }
        __syncthreads();
    }

    int tr = lane >> 2, tc = (lane & 3) << 1;
    #pragma unroll
    for (int mt = 0; mt < 4; mt++) {
        int rbase = m0 + wm * 64 + mt * 16 + tr;
        #pragma unroll
        for (int nt = 0; nt < 4; nt++) {
            int col = n0 + wn * 32 + nt * 8 + tc;
            float b0 = 0.f, b1 = 0.f;
            if (bias) { b0 = bias[col]; b1 = bias[col + 1]; }
            float v0 = acc[mt][nt][0] + b0, v1 = acc[mt][nt][1] + b1;
            float v2 = acc[mt][nt][2] + b0, v3 = acc[mt][nt][3] + b1;
            if (relu) {
                v0 = fmaxf(v0, 0.f); v1 = fmaxf(v1, 0.f);
                v2 = fmaxf(v2, 0.f); v3 = fmaxf(v3, 0.f);
            }
            *(float2*)&C[(size_t)rbase * Nn + col]       = make_float2(v0, v1);
            *(float2*)&C[(size_t)(rbase + 8) * Nn + col] = make_float2(v2, v3);
        }
    }
}

// ---------------- GTVConv aggregate + elu + fused bf16 split (warp per dst) ------
// x2 edge unroll (32 live v-regs) + __launch_bounds__(128,6) -> 24 warps/SM for
// latency hiding. Payload staging + shfl broadcast unchanged.
#define CONV_EDGE(vv, ss, dd)                                                     \
    {                                                                             \
        const float4* hp = (const float4*)(h + (size_t)(ss) * MP_CH);             \
        _Pragma("unroll")                                                         \
        for (int j = 0; j < 4; j++) {                                             \
            vv[j] = hp[lane + 32 * j];                                            \
            dd += fabsf(vv[j].x - hd[j].x) + fabsf(vv[j].y - hd[j].y)             \
                + fabsf(vv[j].z - hd[j].z) + fabsf(vv[j].w - hd[j].w);            \
        }                                                                         \
    }
#define CONV_ACC(vv, gg)                                                          \
    {                                                                             \
        _Pragma("unroll")                                                         \
        for (int j = 0; j < 4; j++) {                                             \
            acc[j].x = fmaf(gg, vv[j].x, acc[j].x);                               \
            acc[j].y = fmaf(gg, vv[j].y, acc[j].y);                               \
            acc[j].z = fmaf(gg, vv[j].z, acc[j].z);                               \
            acc[j].w = fmaf(gg, vv[j].w, acc[j].w);                               \
        }                                                                         \
    }

__global__ __launch_bounds__(128, 6) void k_conv(
    const float* __restrict__ h, const float* __restrict__ bias,
    __nv_bfloat16* __restrict__ Ah, __nv_bfloat16* __restrict__ Al)
{
    int warp = (blockIdx.x * blockDim.x + threadIdx.x) >> 5;
    int lane = threadIdx.x & 31;
    if (warp >= N_NODES) return;
    const float4* hd4 = (const float4*)(h + (size_t)warp * MP_CH);
    float4 hd[4], acc[4];
    #pragma unroll
    for (int j = 0; j < 4; j++) {
        hd[j] = hd4[lane + 32 * j];
        acc[j] = make_float4(0.f, 0.f, 0.f, 0.f);
    }
    float deg = 0.f;
    int p0 = g_rowptr[warp], p1 = g_rowptr[warp + 1];

    for (int base = p0; base < p1; base += 32) {
        int navail = p1 - base;
        if (navail > 32) navail = 32;
        int psrc = 0, pwb = 0;
        if (lane < navail) {
            int2 pp = g_epay[base + lane];
            psrc = pp.x; pwb = pp.y;
        }
        int g = 0;
        for (; g + 2 <= navail; g += 2) {
            int s0 = __shfl_sync(0xffffffffu, psrc, g + 0);
            int w0 = __shfl_sync(0xffffffffu, pwb,  g + 0);
            int s1 = __shfl_sync(0xffffffffu, psrc, g + 1);
            int w1 = __shfl_sync(0xffffffffu, pwb,  g + 1);
            float4 v0[4], v1[4];
            float d0 = 0.f, d1 = 0.f;
            CONV_EDGE(v0, s0, d0);
            CONV_EDGE(v1, s1, d1);
            #pragma unroll
            for (int o = 16; o > 0; o >>= 1) {
                d0 += __shfl_xor_sync(0xffffffffu, d0, o);
                d1 += __shfl_xor_sync(0xffffffffu, d1, o);
            }
            float g0 = __int_as_float(w0) / fmaxf(d0, EPSF);
            float g1 = __int_as_float(w1) / fmaxf(d1, EPSF);
            deg += g0 + g1;
            CONV_ACC(v0, g0);
            CONV_ACC(v1, g1);
        }
        if (g < navail) {
            int s0 = __shfl_sync(0xffffffffu, psrc, g);
            int w0 = __shfl_sync(0xffffffffu, pwb,  g);
            float4 v0[4];
            float d0 = 0.f;
            CONV_EDGE(v0, s0, d0);
            #pragma unroll
            for (int o = 16; o > 0; o >>= 1) d0 += __shfl_xor_sync(0xffffffffu, d0, o);
            float g0 = __int_as_float(w0) / fmaxf(d0, EPSF);
            deg += g0;
            CONV_ACC(v0, g0);
        }
    }

    const float4* b4 = (const float4*)bias;
    ushort4* ph = (ushort4*)(Ah + (size_t)warp * MP_CH);
    ushort4* pl = (ushort4*)(Al + (size_t)warp * MP_CH);
    #pragma unroll
    for (int j = 0; j < 4; j++) {
        float4 bb = b4[lane + 32 * j];
        float o[4];
        o[0] = hd[j].x - DELTAF * (deg * hd[j].x - acc[j].x) + bb.x;
        o[1] = hd[j].y - DELTAF * (deg * hd[j].y - acc[j].y) + bb.y;
        o[2] = hd[j].z - DELTAF * (deg * hd[j].z - acc[j].z) + bb.z;
        o[3] = hd[j].w - DELTAF * (deg * hd[j].w - acc[j].w) + bb.w;
        ushort4 uh, ul;
        unsigned short* puh = (unsigned short*)&uh;
        unsigned short* pul = (unsigned short*)&ul;
        #pragma unroll
        for (int t = 0; t < 4; t++) {
            float e = (o[t] > 0.f) ? o[t] : expm1f(o[t]);
            __nv_bfloat16 hi = __float2bfloat16_rn(e);
            __nv_bfloat16 lo = __float2bfloat16_rn(e - __bfloat162float(hi));
            puh[t] = *(unsigned short*)&hi;
            pul[t] = *(unsigned short*)&lo;
        }
        ph[lane + 32 * j] = uh;
        pl[lane + 32 * j] = ul;
    }
}

// ---------------- s_logits = hid @ Wm2 + bm2 ; fused softmax (warp per row) ------
__global__ __launch_bounds__(256) void k_mlp2(
    const float* __restrict__ hid, const float* __restrict__ Wm2,
    const float* __restrict__ bm2, float* __restrict__ out)
{
    __shared__ float ws[HID_ * KCL];
    for (int i = threadIdx.x; i < HID_ * KCL; i += 256) ws[i] = Wm2[i];
    __syncthreads();
    int warp = threadIdx.x >> 5, lane = threadIdx.x & 31;
    int row = blockIdx.x * 8 + warp;
    if (row >= N_NODES) return;
    float acc[KCL];
    #pragma unroll
    for (int k = 0; k < KCL; k++) acc[k] = 0.f;
    const float4* h4 = (const float4*)(hid + (size_t)row * HID_);
    #pragma unroll
    for (int ii = 0; ii < 2; ii++) {
        int c4 = lane + ii * 32;
        float4 v = h4[c4];
        int cb = c4 * 4;
        #pragma unroll
        for (int k = 0; k < KCL; k++) {
            acc[k] = fmaf(v.x, ws[(cb + 0) * KCL + k],
                     fmaf(v.y, ws[(cb + 1) * KCL + k],
                     fmaf(v.z, ws[(cb + 2) * KCL + k],
                     fmaf(v.w, ws[(cb + 3) * KCL + k], acc[k]))));
        }
    }
    #pragma unroll
    for (int k = 0; k < KCL; k++) {
        #pragma unroll
        for (int o = 16; o > 0; o >>= 1) acc[k] += __shfl_xor_sync(0xffffffffu, acc[k], o);
    }
    if (lane == 0) {
        float v[KCL];
        float m = -1e30f;
        #pragma unroll
        for (int k = 0; k < KCL; k++) {
            v[k] = acc[k] + bm2[k];
            out[(size_t)row * KCL + k] = v[k];
            m = fmaxf(m, v[k]);
        }
        float sum = 0.f;
        #pragma unroll
        for (int k = 0; k < KCL; k++) { v[k] = expf(v[k] - m); sum += v[k]; }
        float inv = 1.f / sum;
        #pragma unroll
        for (int k = 0; k < KCL; k++) g_s[row * KCL + k] = v[k] * inv;
    }
}

// ---------------- fused: TV partials (64 blocks x 4 edges/thread) + quant (10) ---
__global__ __launch_bounds__(1024) void k_tvquant(
    const int* __restrict__ src, const int* __restrict__ dst,
    const float* __restrict__ ew)
{
    __shared__ double shd[1024];
    __shared__ unsigned su[N_NODES];
    __shared__ unsigned hist[256];
    __shared__ unsigned sh_bsel;
    __shared__ unsigned sh_R;
    int tid = threadIdx.x;
    int b = blockIdx.x;
    if (b < 64) {
        double val = 0.0;
        int newcnt = 0;
        #pragma unroll
        for (int it = 0; it < 4; it++) {
            int e = b * 4096 + it * 1024 + tid;
            int si = src[e], di = dst[e];
            float w = ew[e];
            float sum = 0.f;
            #pragma unroll
            for (int k = 0; k < KCL; k++) sum += fabsf(g_s[si * KCL + k] - g_s[di * KCL + k]);
            val += (double)w * (double)sum;
            unsigned key = (unsigned)si * (unsigned)N_NODES + (unsigned)di;
            unsigned m = 1u << (key & 31u);
            unsigned old = atomicOr(&g_bitmap[key >> 5], m);
            newcnt += ((old & m) == 0u) ? 1 : 0;
        }
        #pragma unroll
        for (int o = 16; o > 0; o >>= 1) newcnt += __shfl_xor_sync(0xffffffffu, newcnt, o);
        if ((tid & 31) == 0 && newcnt) atomicAdd(&g_nedges, newcnt);

        shd[tid] = val;
        __syncthreads();
        for (int o = 512; o > 0; o >>= 1) {
            if (tid < o) shd[tid] += shd[tid + o];
            __syncthreads();
        }
        if (tid == 0) g_tv_part[b] = shd[0];
    } else {
        int k = b - 64;
        for (int i = tid; i < N_NODES; i += 1024)
            su[i] = __float_as_uint(g_s[i * KCL + k]);
        if (tid == 0) sh_R = N_NODES - (N_NODES / KCL + 1);   // 7372
        unsigned mask = 0, val = 0;
        #pragma unroll
        for (int r = 0; r < 4; r++) {
            int shift = 24 - 8 * r;
            if (tid < 256) hist[tid] = 0;
            __syncthreads();
            for (int i = tid; i < N_NODES; i += 1024) {
                unsigned u = su[i];
                if ((u & mask) == val) atomicAdd(&hist[(u >> shift) & 255u], 1u);
            }
            __syncthreads();
            if (tid == 0) {
                unsigned R = sh_R, cum = 0, bsel = 255;
                for (int bin = 0; bin < 256; bin++) {
                    unsigned c = hist[bin];
                    if (R < cum + c) { bsel = bin; break; }
                    cum += c;
                }
                sh_bsel = bsel;
                sh_R = R - cum;
            }
            __syncthreads();
            val |= sh_bsel << shift;
            mask |= 0xFFu << shift;
        }
        if (tid == 0) g_quant[k] = __uint_as_float(val);
    }
}

// ---------------- fused: asym partials + final reduction + state clears ----------
__global__ __launch_bounds__(1024) void k_asymfinal(float* __restrict__ out) {
    __shared__ double sh[1024];
    __shared__ int lastflag;
    int tid = threadIdx.x;
    int i = blockIdx.x * 1024 + tid;   // 80 * 1024 = 81920 exact
    float q = g_quant[i % KCL];
    float t = g_s[i] - q;
    double v = (t >= 0.f) ? (double)((KCL - 1) * t) : (double)(-t);
    sh[tid] = v;
    __syncthreads();
    for (int o = 512; o > 0; o >>= 1) {
        if (tid < o) sh[tid] += sh[tid + o];
        __syncthreads();
    }
    if (tid == 0) {
        g_asym_part[blockIdx.x] = sh[0];
        __threadfence();
        lastflag = (atomicAdd(&g_done, 1) == 79) ? 1 : 0;
    }
    __syncthreads();
    if (lastflag) {
        sh[tid] = (tid < 64) ? g_tv_part[tid] : 0.0;
        __syncthreads();
        for (int o = 512; o > 0; o >>= 1) {
            if (tid < o) sh[tid] += sh[tid + o];
            __syncthreads();
        }
        double tvsum = sh[0];
        __syncthreads();
        sh[tid] = (tid < 80) ? g_asym_part[tid] : 0.0;
        __syncthreads();
        for (int o = 512; o > 0; o >>= 1) {
            if (tid < o) sh[tid] += sh[tid + o];
            __syncthreads();
        }
        if (tid == 0) {
            double asum = sh[0];
            double tv = tvsum / (2.0 * (double)g_nedges);
            double denom = (double)N_NODES * (double)(KCL - 1);
            double balv = (denom - asum) / denom;
            out[N_NODES * KCL + 0] = (float)((double)TV_COEFF * tv);
            out[N_NODES * KCL + 1] = (float)((double)BAL_COEFF * balv);
            g_nedges = 0;
            g_done = 0;
        }
        for (int c = tid; c < N_NODES; c += 1024) g_counts[c] = 0;
    }
}

// ---------------- launch ----------------
extern "C" void kernel_launch(void* const* d_in, const int* in_sizes, int n_in,
                              void* d_out, int out_size) {
    const float* x   = (const float*)d_in[0];
    const int*   ei  = (const int*)d_in[1];
    const float* ew  = (const float*)d_in[2];
    const float* W1  = (const float*)d_in[3];
    const float* b1  = (const float*)d_in[4];
    const float* W2  = (const float*)d_in[5];
    const float* b2  = (const float*)d_in[6];
    const float* Wm1 = (const float*)d_in[7];
    const float* bm1 = (const float*)d_in[8];
    const float* Wm2 = (const float*)d_in[9];
    const float* bm2 = (const float*)d_in[10];
    const int* src = ei;
    const int* dst = ei + E_EDGES;
    float* out = (float*)d_out;

    float *pA, *pHid;
    __nv_bfloat16 *pAh, *pAl, *pBh1, *pBl1, *pBh2, *pBl2, *pBh3, *pBl3;
    cudaGetSymbolAddress((void**)&pA,   g_bufA);
    cudaGetSymbolAddress((void**)&pHid, g_hid);
    cudaGetSymbolAddress((void**)&pAh,  g_ah);
    cudaGetSymbolAddress((void**)&pAl,  g_al);
    cudaGetSymbolAddress((void**)&pBh1, g_bh1);
    cudaGetSymbolAddress((void**)&pBl1, g_bl1);
    cudaGetSymbolAddress((void**)&pBh2, g_bh2);
    cudaGetSymbolAddress((void**)&pBl2, g_bl2);
    cudaGetSymbolAddress((void**)&pBh3, g_bh3);
    cudaGetSymbolAddress((void**)&pBl3, g_bl3);

    cudaFuncSetAttribute(k_mma, cudaFuncAttributeMaxDynamicSharedMemorySize, SM_TOTAL);

    static cudaStream_t s2 = nullptr;
    static cudaEvent_t evF = nullptr, ev1 = nullptr, ev2 = nullptr, ev3 = nullptr;
    if (!s2) {
        cudaStreamCreate(&s2);
        cudaEventCreateWithFlags(&evF, cudaEventDisableTiming);
        cudaEventCreateWithFlags(&ev1, cudaEventDisableTiming);
        cudaEventCreateWithFlags(&ev2, cudaEventDisableTiming);
        cudaEventCreateWithFlags(&ev3, cudaEventDisableTiming);
    }

    // submission order chosen so kernel #4 = mma1 and #6 = conv1 (ncu aiming)
    cudaEventRecord(evF, 0);
    cudaStreamWaitEvent(s2, evF, 0);
    k_hist<<<E_EDGES / 1024, 256, 0, s2>>>(src, dst);          // #1
    k_scan<<<1, 1024, 0, s2>>>();                              // #2
    k_fsplit<<<1024 + 64, 256>>>(x, W1, pAh, pAl, pBh1, pBl1); // #3 (main)
    k_mma<<<dim3(MP_CH / 128, N_NODES / 128), 256, SM_TOTAL>>>(pAh, pAl, pBh1, pBl1, nullptr, pA, IN_CH_, MP_CH, 0); // #4
    k_scatter<<<E_EDGES / 1024, 256, 0, s2>>>(src, dst, ew);   // #5 (overlaps mma1)
    cudaEventRecord(ev1, s2);
    cudaStreamWaitEvent(0, ev1, 0);
    k_conv<<<N_NODES / 4, 128>>>(pA, b1, pAh, pAl);            // #6

    k_wsplit<<<dim3(MP_CH / 32, MP_CH / 32), 256, 0, s2>>>(W2, pBh2, pBl2, MP_CH, MP_CH);   // #7
    cudaEventRecord(ev2, s2);
    k_wsplit<<<dim3(HID_ / 32, MP_CH / 32), 256, 0, s2>>>(Wm1, pBh3, pBl3, MP_CH, HID_);    // #8
    cudaEventRecord(ev3, s2);

    cudaStreamWaitEvent(0, ev2, 0);
    k_mma<<<dim3(MP_CH / 128, N_NODES / 128), 256, SM_TOTAL>>>(pAh, pAl, pBh2, pBl2, nullptr, pA, MP_CH, MP_CH, 0);  // #9
    k_conv<<<N_NODES / 4, 128>>>(pA, b2, pAh, pAl);            // #10

    cudaStreamWaitEvent(0, ev3, 0);
    k_mma<<<dim3(HID_ / 128, N_NODES / 128), 256, SM_TOTAL>>>(pAh, pAl, pBh3, pBl3, bm1, pHid, MP_CH, HID_, 1);      // #11
    k_mlp2<<<N_NODES / 8, 256>>>(pHid, Wm2, bm2, out);         // #12

    k_tvquant<<<64 + KCL, 1024>>>(src, dst, ew);               // #13
    k_asymfinal<<<(N_NODES * KCL) / 1024, 1024>>>(out);        // #14
}

// round 14
// speedup vs baseline: 1.0691x; 1.0691x over previous
#include <cuda_runtime.h>
#include <cuda_bf16.h>
#include <cuda_fp16.h>
#include <math.h>

#define N_NODES 8192
#define E_EDGES 262144
#define IN_CH_  128
#define MP_CH   512
#define HID_    256
#define KCL     10
#define EPSF    0.001f
#define DELTAF  0.311f
#define TV_COEFF 0.785f
#define BAL_COEFF 0.514f

// ---------------- scratch (device globals; no allocation allowed) ----------------
__device__ float          g_bufA[N_NODES * MP_CH];
__device__ float          g_hid [N_NODES * HID_];
__device__ float          g_s   [N_NODES * KCL];
__device__ unsigned       g_bitmap[(N_NODES * (size_t)N_NODES) / 32];   // 8 MB
__device__ int            g_counts[N_NODES];       // cleared by tail kernel each call
__device__ int            g_rowptr[N_NODES + 1];
__device__ int            g_offs  [N_NODES];       // scan writes fresh copy each call
__device__ int2           g_epay  [E_EDGES];       // (src, w_bits) sorted by dst
__device__ int            g_nedges;                // cleared by tail kernel
__device__ int            g_done;                  // cleared by tail kernel
__device__ double         g_tv_part[256];
__device__ double         g_asym_part[80];
__device__ float          g_quant[KCL];
__device__ __nv_bfloat16  g_ah [N_NODES * MP_CH];  // A hi (bf16 or fp16 bits)
__device__ __nv_bfloat16  g_al [N_NODES * MP_CH];  // A lo
__device__ __nv_bfloat16  g_bh1[IN_CH_ * MP_CH];   // W1 split (N x K) bf16
__device__ __nv_bfloat16  g_bl1[IN_CH_ * MP_CH];
__device__ __nv_bfloat16  g_bh2[MP_CH * MP_CH];    // W2 fp16-hi (N x K)
__device__ __nv_bfloat16  g_bh3[MP_CH * HID_];     // Wm1 split bf16
__device__ __nv_bfloat16  g_bl3[MP_CH * HID_];

// ---------------- PTX helpers (sm_80-compatible; no arch-gated features) ---------
__device__ __forceinline__ unsigned smem_u32(const void* p) {
    unsigned a;
    asm("{ .reg .u64 t; cvta.to.shared.u64 t, %1; cvt.u32.u64 %0, t; }" : "=r"(a) : "l"(p));
    return a;
}
__device__ __forceinline__ void cp16(unsigned dst, const void* src) {
    asm volatile("cp.async.cg.shared.global [%0], [%1], 16;" :: "r"(dst), "l"(src));
}
__device__ __forceinline__ void cp_commit() {
    asm volatile("cp.async.commit_group;" ::: "memory");
}
__device__ __forceinline__ void cp_wait0() {
    asm volatile("cp.async.wait_group 0;" ::: "memory");
}
__device__ __forceinline__ void cp_wait1() {
    asm volatile("cp.async.wait_group 1;" ::: "memory");
}
__device__ __forceinline__ void ldsm4(unsigned& r0, unsigned& r1, unsigned& r2, unsigned& r3,
                                      unsigned addr) {
    asm volatile("ldmatrix.sync.aligned.m8n8.x4.shared.b16 {%0,%1,%2,%3}, [%4];"
                 : "=r"(r0), "=r"(r1), "=r"(r2), "=r"(r3) : "r"(addr));
}
__device__ __forceinline__ void ldsm2(unsigned& r0, unsigned& r1, unsigned addr) {
    asm volatile("ldmatrix.sync.aligned.m8n8.x2.shared.b16 {%0,%1}, [%2];"
                 : "=r"(r0), "=r"(r1) : "r"(addr));
}
__device__ __forceinline__ void mma16816(float* d, const unsigned* a, const unsigned* b) {
    asm volatile(
        "mma.sync.aligned.m16n8k16.row.col.f32.bf16.bf16.f32 "
        "{%0,%1,%2,%3}, {%4,%5,%6,%7}, {%8,%9}, {%0,%1,%2,%3};"
        : "+f"(d[0]), "+f"(d[1]), "+f"(d[2]), "+f"(d[3])
        : "r"(a[0]), "r"(a[1]), "r"(a[2]), "r"(a[3]), "r"(b[0]), "r"(b[1]));
}
__device__ __forceinline__ void mma16816h(float* d, const unsigned* a, const unsigned* b) {
    asm volatile(
        "mma.sync.aligned.m16n8k16.row.col.f32.f16.f16.f32 "
        "{%0,%1,%2,%3}, {%4,%5,%6,%7}, {%8,%9}, {%0,%1,%2,%3};"
        : "+f"(d[0]), "+f"(d[1]), "+f"(d[2]), "+f"(d[3])
        : "r"(a[0]), "r"(a[1]), "r"(a[2]), "r"(a[3]), "r"(b[0]), "r"(b[1]));
}

// ---------------- CSR build (by dst) + bitmap spot-clear, x4 ILP ----------------
__global__ void k_hist(const int* __restrict__ src, const int* __restrict__ dst) {
    int t = blockIdx.x * blockDim.x + threadIdx.x;   // grid covers E/4
    int4 s4 = ((const int4*)src)[t];
    int4 d4 = ((const int4*)dst)[t];
    atomicAdd(&g_counts[d4.x], 1);
    atomicAdd(&g_counts[d4.y], 1);
    atomicAdd(&g_counts[d4.z], 1);
    atomicAdd(&g_counts[d4.w], 1);
    g_bitmap[((unsigned)s4.x * N_NODES + (unsigned)d4.x) >> 5] = 0u;
    g_bitmap[((unsigned)s4.y * N_NODES + (unsigned)d4.y) >> 5] = 0u;
    g_bitmap[((unsigned)s4.z * N_NODES + (unsigned)d4.z) >> 5] = 0u;
    g_bitmap[((unsigned)s4.w * N_NODES + (unsigned)d4.w) >> 5] = 0u;
}

__global__ void k_scan() {   // single block, 1024 threads, 8 elems each
    __shared__ int tsum[1024];
    int tid = threadIdx.x;
    int base = tid * 8;
    int local[8];
    int s = 0;
    #pragma unroll
    for (int i = 0; i < 8; i++) { local[i] = s; s += g_counts[base + i]; }
    tsum[tid] = s;
    __syncthreads();
    for (int off = 1; off < 1024; off <<= 1) {
        int v = 0;
        if (tid >= off) v = tsum[tid - off];
        __syncthreads();
        if (tid >= off) tsum[tid] += v;
        __syncthreads();
    }
    int prefix = tsum[tid] - s;
    #pragma unroll
    for (int i = 0; i < 8; i++) {
        int v = prefix + local[i];
        g_rowptr[base + i] = v;
        g_offs[base + i] = v;
    }
    if (tid == 1023) g_rowptr[N_NODES] = tsum[1023];
}

__global__ void k_scatter(const int* __restrict__ src, const int* __restrict__ dst,
                          const float* __restrict__ ew) {
    int t = blockIdx.x * blockDim.x + threadIdx.x;   // grid covers E/4
    int4 s4 = ((const int4*)src)[t];
    int4 d4 = ((const int4*)dst)[t];
    float4 w4 = ((const float4*)ew)[t];
    int p0 = atomicAdd(&g_offs[d4.x], 1);
    g_epay[p0] = make_int2(s4.x, __float_as_int(w4.x));
    int p1 = atomicAdd(&g_offs[d4.y], 1);
    g_epay[p1] = make_int2(s4.y, __float_as_int(w4.y));
    int p2 = atomicAdd(&g_offs[d4.z], 1);
    g_epay[p2] = make_int2(s4.z, __float_as_int(w4.z));
    int p3 = atomicAdd(&g_offs[d4.w], 1);
    g_epay[p3] = make_int2(s4.w, __float_as_int(w4.w));
}

// ---------------- wsplit body (transpose + bf16 split) ----------------
__device__ __forceinline__ void wsplit_body(
    const float* __restrict__ W, __nv_bfloat16* __restrict__ Bh,
    __nv_bfloat16* __restrict__ Bl, int Kdim, int Nn,
    int bx, int by, float (*t)[33])
{
    int tid = threadIdx.x;
    int tx = tid & 31, ty = tid >> 5;   // 32 x 8
    int kb = by * 32, nb = bx * 32;
    #pragma unroll
    for (int i = 0; i < 4; i++)
        t[ty + i * 8][tx] = W[(size_t)(kb + ty + i * 8) * Nn + nb + tx];
    __syncthreads();
    #pragma unroll
    for (int i = 0; i < 4; i++) {
        int nl = ty + i * 8;
        float a = t[tx][nl];
        __nv_bfloat16 hi = __float2bfloat16_rn(a);
        __nv_bfloat16 lo = __float2bfloat16_rn(a - __bfloat162float(hi));
        Bh[(size_t)(nb + nl) * Kdim + kb + tx] = hi;
        Bl[(size_t)(nb + nl) * Kdim + kb + tx] = lo;
    }
}

__global__ void k_wsplit(const float* __restrict__ W,
                         __nv_bfloat16* __restrict__ Bh,
                         __nv_bfloat16* __restrict__ Bl, int Kdim, int Nn) {
    __shared__ float t[32][33];
    wsplit_body(W, Bh, Bl, Kdim, Nn, blockIdx.x, blockIdx.y, t);
}

// fp16-hi-only transpose (for the 2-pass fp16 GEMM's B operand)
__global__ void k_wsplit_h(const float* __restrict__ W,
                           __half* __restrict__ Bh, int Kdim, int Nn) {
    __shared__ float t[32][33];
    int tid = threadIdx.x;
    int tx = tid & 31, ty = tid >> 5;
    int kb = blockIdx.y * 32, nb = blockIdx.x * 32;
    #pragma unroll
    for (int i = 0; i < 4; i++)
        t[ty + i * 8][tx] = W[(size_t)(kb + ty + i * 8) * Nn + nb + tx];
    __syncthreads();
    #pragma unroll
    for (int i = 0; i < 4; i++) {
        int nl = ty + i * 8;
        Bh[(size_t)(nb + nl) * Kdim + kb + tx] = __float2half_rn(t[tx][nl]);
    }
}

// ---------------- fused: x split (1024 blocks) + W1 split (64 blocks) ------------
__global__ void k_fsplit(const float* __restrict__ x, const float* __restrict__ W1,
                         __nv_bfloat16* __restrict__ Ah, __nv_bfloat16* __restrict__ Al,
                         __nv_bfloat16* __restrict__ Bh, __nv_bfloat16* __restrict__ Bl) {
    __shared__ float t[32][33];
    int b = blockIdx.x;
    if (b < 1024) {
        int i = b * 256 + threadIdx.x;
        float4 v = ((const float4*)x)[i];
        float f[4] = {v.x, v.y, v.z, v.w};
        __nv_bfloat16 hi[4], lo[4];
        #pragma unroll
        for (int j = 0; j < 4; j++) {
            hi[j] = __float2bfloat16_rn(f[j]);
            lo[j] = __float2bfloat16_rn(f[j] - __bfloat162float(hi[j]));
        }
        __nv_bfloat162* ph = (__nv_bfloat162*)(Ah + i * 4);
        __nv_bfloat162* pl = (__nv_bfloat162*)(Al + i * 4);
        ph[0] = __nv_bfloat162(hi[0], hi[1]);
        ph[1] = __nv_bfloat162(hi[2], hi[3]);
        pl[0] = __nv_bfloat162(lo[0], lo[1]);
        pl[1] = __nv_bfloat162(lo[2], lo[3]);
    } else {
        int bb = b - 1024;
        wsplit_body(W1, Bh, Bl, IN_CH_, MP_CH, bb & 15, bb >> 4, t);
    }
}

// ---------------- HMMA bf16-split GEMM (3-pass) ----------------
#define AH_OFF 0
#define AL_OFF 10240
#define BH_OFF 20480
#define BL_OFF 30720
#define STAGE_BYTES 40960
#define SM_TOTAL (2 * STAGE_BYTES)

__device__ __forceinline__ void load_stage(
    unsigned sbase,
    const __nv_bfloat16* __restrict__ Ah, const __nv_bfloat16* __restrict__ Al,
    const __nv_bfloat16* __restrict__ Bh, const __nv_bfloat16* __restrict__ Bl,
    int m0, int n0, int k0, int Kdim)
{
    int tid = threadIdx.x;
    #pragma unroll
    for (int it = 0; it < 2; it++) {
        int c = it * 256 + tid;
        int row = c >> 2, seg = c & 3;
        unsigned so = row * 80 + seg * 16;
        size_t goa = (size_t)(m0 + row) * Kdim + k0 + seg * 8;
        size_t gob = (size_t)(n0 + row) * Kdim + k0 + seg * 8;
        cp16(sbase + AH_OFF + so, Ah + goa);
        cp16(sbase + AL_OFF + so, Al + goa);
        cp16(sbase + BH_OFF + so, Bh + gob);
        cp16(sbase + BL_OFF + so, Bl + gob);
    }
}

__global__ __launch_bounds__(256) void k_mma(
    const __nv_bfloat16* __restrict__ Ah, const __nv_bfloat16* __restrict__ Al,
    const __nv_bfloat16* __restrict__ Bh, const __nv_bfloat16* __restrict__ Bl,
    const float* __restrict__ bias, float* __restrict__ C,
    int Kdim, int Nn, int relu)
{
    extern __shared__ char smem[];
    unsigned sb = smem_u32(smem);
    int tid = threadIdx.x;
    int wid = tid >> 5, lane = tid & 31;
    int wm = wid >> 2, wn = wid & 3;

    int m0 = blockIdx.y * 128, n0 = blockIdx.x * 128;
    int nch = Kdim >> 5;

    float acc[4][4][4];
    #pragma unroll
    for (int mt = 0; mt < 4; mt++)
        #pragma unroll
        for (int nt = 0; nt < 4; nt++)
            #pragma unroll
            for (int q = 0; q < 4; q++) acc[mt][nt][q] = 0.f;

    load_stage(sb, Ah, Al, Bh, Bl, m0, n0, 0, Kdim);
    cp_commit();

    for (int ch = 0; ch < nch; ch++) {
        unsigned stage = sb + (unsigned)(ch & 1) * STAGE_BYTES;
        if (ch + 1 < nch) {
            load_stage(sb + (unsigned)((ch + 1) & 1) * STAGE_BYTES,
                       Ah, Al, Bh, Bl, m0, n0, (ch + 1) << 5, Kdim);
            cp_commit();
            cp_wait1();
        } else {
            cp_wait0();
        }
        __syncthreads();

        unsigned AsH = stage + AH_OFF, AsL = stage + AL_OFF;
        unsigned BsH = stage + BH_OFF, BsL = stage + BL_OFF;
        #pragma unroll
        for (int k0 = 0; k0 < 32; k0 += 16) {
            unsigned bh[4][2], bl[4][2], ah[4][4], al[4][4];
            int rB = lane & 7, kB = lane & 8;
            #pragma unroll
            for (int nt = 0; nt < 4; nt++) {
                unsigned off = (unsigned)(wn * 32 + nt * 8 + rB) * 80 + (k0 + kB) * 2;
                ldsm2(bh[nt][0], bh[nt][1], BsH + off);
                ldsm2(bl[nt][0], bl[nt][1], BsL + off);
            }
            int rA = lane & 15, kA = (lane >> 4) << 3;
            #pragma unroll
            for (int mt = 0; mt < 4; mt++) {
                unsigned off = (unsigned)(wm * 64 + mt * 16 + rA) * 80 + (k0 + kA) * 2;
                ldsm4(ah[mt][0], ah[mt][1], ah[mt][2], ah[mt][3], AsH + off);
                ldsm4(al[mt][0], al[mt][1], al[mt][2], al[mt][3], AsL + off);
            }
            #pragma unroll
            for (int mt = 0; mt < 4; mt++)
                #pragma unroll
                for (int nt = 0; nt < 4; nt++) {
                    mma16816(acc[mt][nt], ah[mt], bh[nt]);
                    mma16816(acc[mt][nt], ah[mt], bl[nt]);
                    mma16816(acc[mt][nt], al[mt], bh[nt]);
                }
        }
        __syncthreads();
    }

    int tr = lane >> 2, tc = (lane & 3) << 1;
    #pragma unroll
    for (int mt = 0; mt < 4; mt++) {
        int rbase = m0 + wm * 64 + mt * 16 + tr;
        #pragma unroll
        for (int nt = 0; nt < 4; nt++) {
            int col = n0 + wn * 32 + nt * 8 + tc;
            float b0 = 0.f, b1 = 0.f;
            if (bias) { b0 = bias[col]; b1 = bias[col + 1]; }
            float v0 = acc[mt][nt][0] + b0, v1 = acc[mt][nt][1] + b1;
            float v2 = acc[mt][nt][2] + b0, v3 = acc[mt][nt][3] + b1;
            if (relu) {
                v0 = fmaxf(v0, 0.f); v1 = fmaxf(v1, 0.f);
                v2 = fmaxf(v2, 0.f); v3 = fmaxf(v3, 0.f);
            }
            *(float2*)&C[(size_t)rbase * Nn + col]       = make_float2(v0, v1);
            *(float2*)&C[(size_t)(rbase + 8) * Nn + col] = make_float2(v2, v3);
        }
    }
}

// ---------------- HMMA fp16 2-pass GEMM: D = Ah*Bh + Al*Bh ----------------
// A split exactly into fp16 hi+lo; B rounded to fp16. err ~ A*(B-fp16(B)) ~ 2^-11.
#define H_AH 0
#define H_AL 10240
#define H_BH 20480
#define H_STAGE 30720
#define SM_TOTAL_H (2 * H_STAGE)

__global__ __launch_bounds__(256) void k_mmah(
    const __half* __restrict__ Ah, const __half* __restrict__ Al,
    const __half* __restrict__ Bh, float* __restrict__ C,
    int Kdim, int Nn)
{
    extern __shared__ char smem[];
    unsigned sb = smem_u32(smem);
    int tid = threadIdx.x;
    int wid = tid >> 5, lane = tid & 31;
    int wm = wid >> 2, wn = wid & 3;

    int m0 = blockIdx.y * 128, n0 = blockIdx.x * 128;
    int nch = Kdim >> 5;

    float acc[4][4][4];
    #pragma unroll
    for (int mt = 0; mt < 4; mt++)
        #pragma unroll
        for (int nt = 0; nt < 4; nt++)
            #pragma unroll
            for (int q = 0; q < 4; q++) acc[mt][nt][q] = 0.f;

    // prologue load
    {
        #pragma unroll
        for (int it = 0; it < 2; it++) {
            int c = it * 256 + tid;
            int row = c >> 2, seg = c & 3;
            unsigned so = row * 80 + seg * 16;
            size_t goa = (size_t)(m0 + row) * Kdim + seg * 8;
            size_t gob = (size_t)(n0 + row) * Kdim + seg * 8;
            cp16(sb + H_AH + so, Ah + goa);
            cp16(sb + H_AL + so, Al + goa);
            cp16(sb + H_BH + so, Bh + gob);
        }
        cp_commit();
    }

    for (int ch = 0; ch < nch; ch++) {
        unsigned stage = sb + (unsigned)(ch & 1) * H_STAGE;
        if (ch + 1 < nch) {
            unsigned nstage = sb + (unsigned)((ch + 1) & 1) * H_STAGE;
            int k0g = (ch + 1) << 5;
            #pragma unroll
            for (int it = 0; it < 2; it++) {
                int c = it * 256 + tid;
                int row = c >> 2, seg = c & 3;
                unsigned so = row * 80 + seg * 16;
                size_t goa = (size_t)(m0 + row) * Kdim + k0g + seg * 8;
                size_t gob = (size_t)(n0 + row) * Kdim + k0g + seg * 8;
                cp16(nstage + H_AH + so, Ah + goa);
                cp16(nstage + H_AL + so, Al + goa);
                cp16(nstage + H_BH + so, Bh + gob);
            }
            cp_commit();
            cp_wait1();
        } else {
            cp_wait0();
        }
        __syncthreads();

        unsigned AsH = stage + H_AH, AsL = stage + H_AL, BsH = stage + H_BH;
        #pragma unroll
        for (int k0 = 0; k0 < 32; k0 += 16) {
            unsigned bh[4][2], ah[4][4], al[4][4];
            int rB = lane & 7, kB = lane & 8;
            #pragma unroll
            for (int nt = 0; nt < 4; nt++) {
                unsigned off = (unsigned)(wn * 32 + nt * 8 + rB) * 80 + (k0 + kB) * 2;
                ldsm2(bh[nt][0], bh[nt][1], BsH + off);
            }
            int rA = lane & 15, kA = (lane >> 4) << 3;
            #pragma unroll
            for (int mt = 0; mt < 4; mt++) {
                unsigned off = (unsigned)(wm * 64 + mt * 16 + rA) * 80 + (k0 + kA) * 2;
                ldsm4(ah[mt][0], ah[mt][1], ah[mt][2], ah[mt][3], AsH + off);
                ldsm4(al[mt][0], al[mt][1], al[mt][2], al[mt][3], AsL + off);
            }
            #pragma unroll
            for (int mt = 0; mt < 4; mt++)
                #pragma unroll
                for (int nt = 0; nt < 4; nt++) {
                    mma16816h(acc[mt][nt], ah[mt], bh[nt]);
                    mma16816h(acc[mt][nt], al[mt], bh[nt]);
                }
        }
        __syncthreads();
    }

    int tr = lane >> 2, tc = (lane & 3) << 1;
    #pragma unroll
    for (int mt = 0; mt < 4; mt++) {
        int rbase = m0 + wm * 64 + mt * 16 + tr;
        #pragma unroll
        for (int nt = 0; nt < 4; nt++) {
            int col = n0 + wn * 32 + nt * 8 + tc;
            *(float2*)&C[(size_t)rbase * Nn + col] =
                make_float2(acc[mt][nt][0], acc[mt][nt][1]);
            *(float2*)&C[(size_t)(rbase + 8) * Nn + col] =
                make_float2(acc[mt][nt][2], acc[mt][nt][3]);
        }
    }
}

// ---------------- GTVConv aggregate + elu + fused split (warp per dst) -----------
// fp32 float4 gathers; payload staging + shfl broadcast; x4 edge unroll; (128,4).
// F16OUT: write fp16 hi/lo (for fp16 GEMM) else bf16 hi/lo.
#define CONV_EDGE(vv, ss, dd)                                                     \
    {                                                                             \
        const float4* hp = (const float4*)(h + (size_t)(ss) * MP_CH);             \
        _Pragma("unroll")                                                         \
        for (int j = 0; j < 4; j++) {                                             \
            vv[j] = hp[lane + 32 * j];                                            \
            dd += fabsf(vv[j].x - hd[j].x) + fabsf(vv[j].y - hd[j].y)             \
                + fabsf(vv[j].z - hd[j].z) + fabsf(vv[j].w - hd[j].w);            \
        }                                                                         \
    }
#define CONV_ACC(vv, gg)                                                          \
    {                                                                             \
        _Pragma("unroll")                                                         \
        for (int j = 0; j < 4; j++) {                                             \
            acc[j].x = fmaf(gg, vv[j].x, acc[j].x);                               \
            acc[j].y = fmaf(gg, vv[j].y, acc[j].y);                               \
            acc[j].z = fmaf(gg, vv[j].z, acc[j].z);                               \
            acc[j].w = fmaf(gg, vv[j].w, acc[j].w);                               \
        }                                                                         \
    }

template<bool F16OUT>
__global__ __launch_bounds__(128, 4) void k_conv(
    const float* __restrict__ h, const float* __restrict__ bias,
    __nv_bfloat16* __restrict__ Ah, __nv_bfloat16* __restrict__ Al)
{
    int warp = (blockIdx.x * blockDim.x + threadIdx.x) >> 5;
    int lane = threadIdx.x & 31;
    if (warp >= N_NODES) return;
    const float4* hd4 = (const float4*)(h + (size_t)warp * MP_CH);
    float4 hd[4], acc[4];
    #pragma unroll
    for (int j = 0; j < 4; j++) {
        hd[j] = hd4[lane + 32 * j];
        acc[j] = make_float4(0.f, 0.f, 0.f, 0.f);
    }
    float deg = 0.f;
    int p0 = g_rowptr[warp], p1 = g_rowptr[warp + 1];

    for (int base = p0; base < p1; base += 32) {
        int navail = p1 - base;
        if (navail > 32) navail = 32;
        int psrc = 0, pwb = 0;
        if (lane < navail) {
            int2 pp = g_epay[base + lane];
            psrc = pp.x; pwb = pp.y;
        }
        int g = 0;
        for (; g + 4 <= navail; g += 4) {
            int s0 = __shfl_sync(0xffffffffu, psrc, g + 0);
            int w0 = __shfl_sync(0xffffffffu, pwb,  g + 0);
            int s1 = __shfl_sync(0xffffffffu, psrc, g + 1);
            int w1 = __shfl_sync(0xffffffffu, pwb,  g + 1);
            int s2 = __shfl_sync(0xffffffffu, psrc, g + 2);
            int w2 = __shfl_sync(0xffffffffu, pwb,  g + 2);
            int s3 = __shfl_sync(0xffffffffu, psrc, g + 3);
            int w3 = __shfl_sync(0xffffffffu, pwb,  g + 3);
            float4 v0[4], v1[4], v2[4], v3[4];
            float d0 = 0.f, d1 = 0.f, d2 = 0.f, d3 = 0.f;
            CONV_EDGE(v0, s0, d0);
            CONV_EDGE(v1, s1, d1);
            CONV_EDGE(v2, s2, d2);
            CONV_EDGE(v3, s3, d3);
            #pragma unroll
            for (int o = 16; o > 0; o >>= 1) {
                d0 += __shfl_xor_sync(0xffffffffu, d0, o);
                d1 += __shfl_xor_sync(0xffffffffu, d1, o);
                d2 += __shfl_xor_sync(0xffffffffu, d2, o);
                d3 += __shfl_xor_sync(0xffffffffu, d3, o);
            }
            float g0 = __int_as_float(w0) / fmaxf(d0, EPSF);
            float g1 = __int_as_float(w1) / fmaxf(d1, EPSF);
            float g2 = __int_as_float(w2) / fmaxf(d2, EPSF);
            float g3 = __int_as_float(w3) / fmaxf(d3, EPSF);
            deg += (g0 + g1) + (g2 + g3);
            CONV_ACC(v0, g0);
            CONV_ACC(v1, g1);
            CONV_ACC(v2, g2);
            CONV_ACC(v3, g3);
        }
        for (; g < navail; g++) {
            int s0 = __shfl_sync(0xffffffffu, psrc, g);
            int w0 = __shfl_sync(0xffffffffu, pwb,  g);
            float4 v0[4];
            float d0 = 0.f;
            CONV_EDGE(v0, s0, d0);
            #pragma unroll
            for (int o = 16; o > 0; o >>= 1) d0 += __shfl_xor_sync(0xffffffffu, d0, o);
            float g0 = __int_as_float(w0) / fmaxf(d0, EPSF);
            deg += g0;
            CONV_ACC(v0, g0);
        }
    }

    const float4* b4 = (const float4*)bias;
    ushort4* ph = (ushort4*)(Ah + (size_t)warp * MP_CH);
    ushort4* pl = (ushort4*)(Al + (size_t)warp * MP_CH);
    #pragma unroll
    for (int j = 0; j < 4; j++) {
        float4 bb = b4[lane + 32 * j];
        float o[4];
        o[0] = hd[j].x - DELTAF * (deg * hd[j].x - acc[j].x) + bb.x;
        o[1] = hd[j].y - DELTAF * (deg * hd[j].y - acc[j].y) + bb.y;
        o[2] = hd[j].z - DELTAF * (deg * hd[j].z - acc[j].z) + bb.z;
        o[3] = hd[j].w - DELTAF * (deg * hd[j].w - acc[j].w) + bb.w;
        ushort4 uh, ul;
        unsigned short* puh = (unsigned short*)&uh;
        unsigned short* pul = (unsigned short*)&ul;
        #pragma unroll
        for (int t = 0; t < 4; t++) {
            float e = (o[t] > 0.f) ? o[t] : expm1f(o[t]);
            if (F16OUT) {
                __half hi = __float2half_rn(e);
                __half lo = __float2half_rn(e - __half2float(hi));
                puh[t] = *(unsigned short*)&hi;
                pul[t] = *(unsigned short*)&lo;
            } else {
                __nv_bfloat16 hi = __float2bfloat16_rn(e);
                __nv_bfloat16 lo = __float2bfloat16_rn(e - __bfloat162float(hi));
                puh[t] = *(unsigned short*)&hi;
                pul[t] = *(unsigned short*)&lo;
            }
        }
        ph[lane + 32 * j] = uh;
        pl[lane + 32 * j] = ul;
    }
}

// ---------------- s_logits = hid @ Wm2 + bm2 ; fused softmax (warp per row) ------
__global__ __launch_bounds__(256) void k_mlp2(
    const float* __restrict__ hid, const float* __restrict__ Wm2,
    const float* __restrict__ bm2, float* __restrict__ out)
{
    __shared__ float ws[HID_ * KCL];
    for (int i = threadIdx.x; i < HID_ * KCL; i += 256) ws[i] = Wm2[i];
    __syncthreads();
    int warp = threadIdx.x >> 5, lane = threadIdx.x & 31;
    int row = blockIdx.x * 8 + warp;
    if (row >= N_NODES) return;
    float acc[KCL];
    #pragma unroll
    for (int k = 0; k < KCL; k++) acc[k] = 0.f;
    const float4* h4 = (const float4*)(hid + (size_t)row * HID_);
    #pragma unroll
    for (int ii = 0; ii < 2; ii++) {
        int c4 = lane + ii * 32;
        float4 v = h4[c4];
        int cb = c4 * 4;
        #pragma unroll
        for (int k = 0; k < KCL; k++) {
            acc[k] = fmaf(v.x, ws[(cb + 0) * KCL + k],
                     fmaf(v.y, ws[(cb + 1) * KCL + k],
                     fmaf(v.z, ws[(cb + 2) * KCL + k],
                     fmaf(v.w, ws[(cb + 3) * KCL + k], acc[k]))));
        }
    }
    #pragma unroll
    for (int k = 0; k < KCL; k++) {
        #pragma unroll
        for (int o = 16; o > 0; o >>= 1) acc[k] += __shfl_xor_sync(0xffffffffu, acc[k], o);
    }
    if (lane == 0) {
        float v[KCL];
        float m = -1e30f;
        #pragma unroll
        for (int k = 0; k < KCL; k++) {
            v[k] = acc[k] + bm2[k];
            out[(size_t)row * KCL + k] = v[k];
            m = fmaxf(m, v[k]);
        }
        float sum = 0.f;
        #pragma unroll
        for (int k = 0; k < KCL; k++) { v[k] = expf(v[k] - m); sum += v[k]; }
        float inv = 1.f / sum;
        #pragma unroll
        for (int k = 0; k < KCL; k++) g_s[row * KCL + k] = v[k] * inv;
    }
}

// ---------------- fused: TV partials (256 blocks) + quant radix-select (10) -----
__global__ __launch_bounds__(1024) void k_tvquant(
    const int* __restrict__ src, const int* __restrict__ dst,
    const float* __restrict__ ew)
{
    __shared__ double shd[1024];
    __shared__ unsigned su[N_NODES];
    __shared__ unsigned hist[256];
    __shared__ unsigned sh_bsel;
    __shared__ unsigned sh_R;
    int tid = threadIdx.x;
    int b = blockIdx.x;
    if (b < 256) {
        int e = b * 1024 + tid;
        int si = src[e], di = dst[e];
        float w = ew[e];
        float sum = 0.f;
        #pragma unroll
        for (int k = 0; k < KCL; k++) sum += fabsf(g_s[si * KCL + k] - g_s[di * KCL + k]);
        double val = (double)w * (double)sum;

        unsigned key = (unsigned)si * (unsigned)N_NODES + (unsigned)di;
        unsigned m = 1u << (key & 31u);
        unsigned old = atomicOr(&g_bitmap[key >> 5], m);
        int isnew = ((old & m) == 0u) ? 1 : 0;
        unsigned bal = __ballot_sync(0xffffffffu, isnew);
        if ((tid & 31) == 0) atomicAdd(&g_nedges, __popc(bal));

        shd[tid] = val;
        __syncthreads();
        for (int o = 512; o > 0; o >>= 1) {
            if (tid < o) shd[tid] += shd[tid + o];
            __syncthreads();
        }
        if (tid == 0) g_tv_part[b] = shd[0];
    } else {
        int k = b - 256;
        for (int i = tid; i < N_NODES; i += 1024)
            su[i] = __float_as_uint(g_s[i * KCL + k]);
        if (tid == 0) sh_R = N_NODES - (N_NODES / KCL + 1);   // 7372
        unsigned mask = 0, val = 0;
        #pragma unroll
        for (int r = 0; r < 4; r++) {
            int shift = 24 - 8 * r;
            if (tid < 256) hist[tid] = 0;
            __syncthreads();
            for (int i = tid; i < N_NODES; i += 1024) {
                unsigned u = su[i];
                if ((u & mask) == val) atomicAdd(&hist[(u >> shift) & 255u], 1u);
            }
            __syncthreads();
            if (tid == 0) {
                unsigned R = sh_R, cum = 0, bsel = 255;
                for (int bin = 0; bin < 256; bin++) {
                    unsigned c = hist[bin];
                    if (R < cum + c) { bsel = bin; break; }
                    cum += c;
                }
                sh_bsel = bsel;
                sh_R = R - cum;
            }
            __syncthreads();
            val |= sh_bsel << shift;
            mask |= 0xFFu << shift;
        }
        if (tid == 0) g_quant[k] = __uint_as_float(val);
    }
}

// ---------------- fused: asym partials + final reduction + state clears ----------
__global__ __launch_bounds__(1024) void k_asymfinal(float* __restrict__ out) {
    __shared__ double sh[1024];
    __shared__ int lastflag;
    int tid = threadIdx.x;
    int i = blockIdx.x * 1024 + tid;   // 80 * 1024 = 81920 exact
    float q = g_quant[i % KCL];
    float t = g_s[i] - q;
    double v = (t >= 0.f) ? (double)((KCL - 1) * t) : (double)(-t);
    sh[tid] = v;
    __syncthreads();
    for (int o = 512; o > 0; o >>= 1) {
        if (tid < o) sh[tid] += sh[tid + o];
        __syncthreads();
    }
    if (tid == 0) {
        g_asym_part[blockIdx.x] = sh[0];
        __threadfence();
        lastflag = (atomicAdd(&g_done, 1) == 79) ? 1 : 0;
    }
    __syncthreads();
    if (lastflag) {
        sh[tid] = (tid < 256) ? g_tv_part[tid] : 0.0;
        __syncthreads();
        for (int o = 512; o > 0; o >>= 1) {
            if (tid < o) sh[tid] += sh[tid + o];
            __syncthreads();
        }
        double tvsum = sh[0];
        __syncthreads();
        sh[tid] = (tid < 80) ? g_asym_part[tid] : 0.0;
        __syncthreads();
        for (int o = 512; o > 0; o >>= 1) {
            if (tid < o) sh[tid] += sh[tid + o];
            __syncthreads();
        }
        if (tid == 0) {
            double asum = sh[0];
            double tv = tvsum / (2.0 * (double)g_nedges);
            double denom = (double)N_NODES * (double)(KCL - 1);
            double balv = (denom - asum) / denom;
            out[N_NODES * KCL + 0] = (float)((double)TV_COEFF * tv);
            out[N_NODES * KCL + 1] = (float)((double)BAL_COEFF * balv);
            g_nedges = 0;
            g_done = 0;
        }
        for (int c = tid; c < N_NODES; c += 1024) g_counts[c] = 0;
    }
}

// ---------------- launch ----------------
extern "C" void kernel_launch(void* const* d_in, const int* in_sizes, int n_in,
                              void* d_out, int out_size) {
    const float* x   = (const float*)d_in[0];
    const int*   ei  = (const int*)d_in[1];
    const float* ew  = (const float*)d_in[2];
    const float* W1  = (const float*)d_in[3];
    const float* b1  = (const float*)d_in[4];
    const float* W2  = (const float*)d_in[5];
    const float* b2  = (const float*)d_in[6];
    const float* Wm1 = (const float*)d_in[7];
    const float* bm1 = (const float*)d_in[8];
    const float* Wm2 = (const float*)d_in[9];
    const float* bm2 = (const float*)d_in[10];
    const int* src = ei;
    const int* dst = ei + E_EDGES;
    float* out = (float*)d_out;

    float *pA, *pHid;
    __nv_bfloat16 *pAh, *pAl, *pBh1, *pBl1, *pBh2, *pBh3, *pBl3;
    cudaGetSymbolAddress((void**)&pA,   g_bufA);
    cudaGetSymbolAddress((void**)&pHid, g_hid);
    cudaGetSymbolAddress((void**)&pAh,  g_ah);
    cudaGetSymbolAddress((void**)&pAl,  g_al);
    cudaGetSymbolAddress((void**)&pBh1, g_bh1);
    cudaGetSymbolAddress((void**)&pBl1, g_bl1);
    cudaGetSymbolAddress((void**)&pBh2, g_bh2);
    cudaGetSymbolAddress((void**)&pBh3, g_bh3);
    cudaGetSymbolAddress((void**)&pBl3, g_bl3);

    cudaFuncSetAttribute(k_mma,  cudaFuncAttributeMaxDynamicSharedMemorySize, SM_TOTAL);
    cudaFuncSetAttribute(k_mmah, cudaFuncAttributeMaxDynamicSharedMemorySize, SM_TOTAL_H);

    static cudaStream_t s2 = nullptr;
    static cudaEvent_t evF = nullptr, ev1 = nullptr, ev2 = nullptr, ev3 = nullptr;
    if (!s2) {
        cudaStreamCreate(&s2);
        cudaEventCreateWithFlags(&evF, cudaEventDisableTiming);
        cudaEventCreateWithFlags(&ev1, cudaEventDisableTiming);
        cudaEventCreateWithFlags(&ev2, cudaEventDisableTiming);
        cudaEventCreateWithFlags(&ev3, cudaEventDisableTiming);
    }

    // submission order: #4 = mma1 (profiler window)
    cudaEventRecord(evF, 0);
    cudaStreamWaitEvent(s2, evF, 0);
    k_hist<<<E_EDGES / 1024, 256, 0, s2>>>(src, dst);          // #1
    k_scan<<<1, 1024, 0, s2>>>();                              // #2
    k_fsplit<<<1024 + 64, 256>>>(x, W1, pAh, pAl, pBh1, pBl1); // #3 (main)
    k_mma<<<dim3(MP_CH / 128, N_NODES / 128), 256, SM_TOTAL>>>(pAh, pAl, pBh1, pBl1, nullptr, pA, IN_CH_, MP_CH, 0); // #4
    k_scatter<<<E_EDGES / 1024, 256, 0, s2>>>(src, dst, ew);   // #5 (overlaps mma1)
    cudaEventRecord(ev1, s2);
    cudaStreamWaitEvent(0, ev1, 0);
    k_conv<true><<<N_NODES / 4, 128>>>(pA, b1, pAh, pAl);      // #6 (fp16 out)

    k_wsplit_h<<<dim3(MP_CH / 32, MP_CH / 32), 256, 0, s2>>>(W2, (__half*)pBh2, MP_CH, MP_CH);  // #7
    cudaEventRecord(ev2, s2);
    k_wsplit<<<dim3(HID_ / 32, MP_CH / 32), 256, 0, s2>>>(Wm1, pBh3, pBl3, MP_CH, HID_);        // #8
    cudaEventRecord(ev3, s2);

    cudaStreamWaitEvent(0, ev2, 0);
    k_mmah<<<dim3(MP_CH / 128, N_NODES / 128), 256, SM_TOTAL_H>>>(
        (const __half*)pAh, (const __half*)pAl, (const __half*)pBh2, pA, MP_CH, MP_CH);          // #9
    k_conv<false><<<N_NODES / 4, 128>>>(pA, b2, pAh, pAl);     // #10 (bf16 out)

    cudaStreamWaitEvent(0, ev3, 0);
    k_mma<<<dim3(HID_ / 128, N_NODES / 128), 256, SM_TOTAL>>>(pAh, pAl, pBh3, pBl3, bm1, pHid, MP_CH, HID_, 1);      // #11
    k_mlp2<<<N_NODES / 8, 256>>>(pHid, Wm2, bm2, out);         // #12

    k_tvquant<<<256 + KCL, 1024>>>(src, dst, ew);              // #13
    k_asymfinal<<<(N_NODES * KCL) / 1024, 1024>>>(out);        // #14
}

// round 15
// speedup vs baseline: 1.1161x; 1.0440x over previous
#include <cuda_runtime.h>
#include <cuda_bf16.h>
#include <cuda_fp16.h>
#include <math.h>

#define N_NODES 8192
#define E_EDGES 262144
#define IN_CH_  128
#define MP_CH   512
#define HID_    256
#define KCL     10
#define EPSF    0.001f
#define DELTAF  0.311f
#define TV_COEFF 0.785f
#define BAL_COEFF 0.514f

// ---------------- scratch (device globals; no allocation allowed) ----------------
__device__ float    g_bufA[N_NODES * MP_CH];
__device__ float    g_hid [N_NODES * HID_];
__device__ float    g_s   [N_NODES * KCL];
__device__ unsigned g_bitmap[(N_NODES * (size_t)N_NODES) / 32];   // 8 MB
__device__ int      g_counts[N_NODES];       // cleared by tail kernel each call
__device__ int      g_rowptr[N_NODES + 1];
__device__ int      g_offs  [N_NODES];       // scan writes fresh copy each call
__device__ int2     g_epay  [E_EDGES];       // (src, w_bits) sorted by dst
__device__ int      g_nedges;                // cleared by tail kernel
__device__ int      g_done;                  // cleared by tail kernel
__device__ double   g_tv_part[256];
__device__ double   g_asym_part[80];
__device__ float    g_quant[KCL];
__device__ __half   g_ah [N_NODES * MP_CH];  // A hi (fp16 split)
__device__ __half   g_al [N_NODES * MP_CH];  // A lo
__device__ __half   g_bh1[IN_CH_ * MP_CH];   // W1 fp16-hi (N x K)
__device__ __half   g_bh2[MP_CH * MP_CH];    // W2 fp16-hi
__device__ __half   g_bh3[MP_CH * HID_];     // Wm1 fp16-hi

// ---------------- PTX helpers (sm_80-compatible; no arch-gated features) ---------
__device__ __forceinline__ unsigned smem_u32(const void* p) {
    unsigned a;
    asm("{ .reg .u64 t; cvta.to.shared.u64 t, %1; cvt.u32.u64 %0, t; }" : "=r"(a) : "l"(p));
    return a;
}
__device__ __forceinline__ void cp16(unsigned dst, const void* src) {
    asm volatile("cp.async.cg.shared.global [%0], [%1], 16;" :: "r"(dst), "l"(src));
}
__device__ __forceinline__ void cp_commit() {
    asm volatile("cp.async.commit_group;" ::: "memory");
}
__device__ __forceinline__ void cp_wait0() {
    asm volatile("cp.async.wait_group 0;" ::: "memory");
}
__device__ __forceinline__ void cp_wait1() {
    asm volatile("cp.async.wait_group 1;" ::: "memory");
}
__device__ __forceinline__ void ldsm4(unsigned& r0, unsigned& r1, unsigned& r2, unsigned& r3,
                                      unsigned addr) {
    asm volatile("ldmatrix.sync.aligned.m8n8.x4.shared.b16 {%0,%1,%2,%3}, [%4];"
                 : "=r"(r0), "=r"(r1), "=r"(r2), "=r"(r3) : "r"(addr));
}
__device__ __forceinline__ void ldsm2(unsigned& r0, unsigned& r1, unsigned addr) {
    asm volatile("ldmatrix.sync.aligned.m8n8.x2.shared.b16 {%0,%1}, [%2];"
                 : "=r"(r0), "=r"(r1) : "r"(addr));
}
__device__ __forceinline__ void mma16816h(float* d, const unsigned* a, const unsigned* b) {
    asm volatile(
        "mma.sync.aligned.m16n8k16.row.col.f32.f16.f16.f32 "
        "{%0,%1,%2,%3}, {%4,%5,%6,%7}, {%8,%9}, {%0,%1,%2,%3};"
        : "+f"(d[0]), "+f"(d[1]), "+f"(d[2]), "+f"(d[3])
        : "r"(a[0]), "r"(a[1]), "r"(a[2]), "r"(a[3]), "r"(b[0]), "r"(b[1]));
}

// ---------------- CSR build (by dst) + bitmap spot-clear, x4 ILP ----------------
__global__ void k_hist(const int* __restrict__ src, const int* __restrict__ dst) {
    int t = blockIdx.x * blockDim.x + threadIdx.x;   // grid covers E/4
    int4 s4 = ((const int4*)src)[t];
    int4 d4 = ((const int4*)dst)[t];
    atomicAdd(&g_counts[d4.x], 1);
    atomicAdd(&g_counts[d4.y], 1);
    atomicAdd(&g_counts[d4.z], 1);
    atomicAdd(&g_counts[d4.w], 1);
    g_bitmap[((unsigned)s4.x * N_NODES + (unsigned)d4.x) >> 5] = 0u;
    g_bitmap[((unsigned)s4.y * N_NODES + (unsigned)d4.y) >> 5] = 0u;
    g_bitmap[((unsigned)s4.z * N_NODES + (unsigned)d4.z) >> 5] = 0u;
    g_bitmap[((unsigned)s4.w * N_NODES + (unsigned)d4.w) >> 5] = 0u;
}

__global__ void k_scan() {   // single block, 1024 threads, 8 elems each
    __shared__ int tsum[1024];
    int tid = threadIdx.x;
    int base = tid * 8;
    int local[8];
    int s = 0;
    #pragma unroll
    for (int i = 0; i < 8; i++) { local[i] = s; s += g_counts[base + i]; }
    tsum[tid] = s;
    __syncthreads();
    for (int off = 1; off < 1024; off <<= 1) {
        int v = 0;
        if (tid >= off) v = tsum[tid - off];
        __syncthreads();
        if (tid >= off) tsum[tid] += v;
        __syncthreads();
    }
    int prefix = tsum[tid] - s;
    #pragma unroll
    for (int i = 0; i < 8; i++) {
        int v = prefix + local[i];
        g_rowptr[base + i] = v;
        g_offs[base + i] = v;
    }
    if (tid == 1023) g_rowptr[N_NODES] = tsum[1023];
}

__global__ void k_scatter(const int* __restrict__ src, const int* __restrict__ dst,
                          const float* __restrict__ ew) {
    int t = blockIdx.x * blockDim.x + threadIdx.x;   // grid covers E/4
    int4 s4 = ((const int4*)src)[t];
    int4 d4 = ((const int4*)dst)[t];
    float4 w4 = ((const float4*)ew)[t];
    int p0 = atomicAdd(&g_offs[d4.x], 1);
    g_epay[p0] = make_int2(s4.x, __float_as_int(w4.x));
    int p1 = atomicAdd(&g_offs[d4.y], 1);
    g_epay[p1] = make_int2(s4.y, __float_as_int(w4.y));
    int p2 = atomicAdd(&g_offs[d4.z], 1);
    g_epay[p2] = make_int2(s4.z, __float_as_int(w4.z));
    int p3 = atomicAdd(&g_offs[d4.w], 1);
    g_epay[p3] = make_int2(s4.w, __float_as_int(w4.w));
}

// ---------------- fp16-hi transpose body: W[K x N] -> Bh[N x K] ----------------
__device__ __forceinline__ void wsplit_h_body(
    const float* __restrict__ W, __half* __restrict__ Bh,
    int Kdim, int Nn, int bx, int by, float (*t)[33])
{
    int tid = threadIdx.x;
    int tx = tid & 31, ty = tid >> 5;   // 32 x 8
    int kb = by * 32, nb = bx * 32;
    #pragma unroll
    for (int i = 0; i < 4; i++)
        t[ty + i * 8][tx] = W[(size_t)(kb + ty + i * 8) * Nn + nb + tx];
    __syncthreads();
    #pragma unroll
    for (int i = 0; i < 4; i++) {
        int nl = ty + i * 8;
        Bh[(size_t)(nb + nl) * Kdim + kb + tx] = __float2half_rn(t[tx][nl]);
    }
}

__global__ void k_wsplit_h(const float* __restrict__ W,
                           __half* __restrict__ Bh, int Kdim, int Nn) {
    __shared__ float t[32][33];
    wsplit_h_body(W, Bh, Kdim, Nn, blockIdx.x, blockIdx.y, t);
}

// ---------------- fused: x fp16 split (1024 blocks) + W1 fp16-hi (64 blocks) -----
__global__ void k_fsplit(const float* __restrict__ x, const float* __restrict__ W1,
                         __half* __restrict__ Ah, __half* __restrict__ Al,
                         __half* __restrict__ Bh) {
    __shared__ float t[32][33];
    int b = blockIdx.x;
    if (b < 1024) {
        int i = b * 256 + threadIdx.x;
        float4 v = ((const float4*)x)[i];
        float f[4] = {v.x, v.y, v.z, v.w};
        __half hi[4], lo[4];
        #pragma unroll
        for (int j = 0; j < 4; j++) {
            hi[j] = __float2half_rn(f[j]);
            lo[j] = __float2half_rn(f[j] - __half2float(hi[j]));
        }
        __half2* ph = (__half2*)(Ah + i * 4);
        __half2* pl = (__half2*)(Al + i * 4);
        ph[0] = __half2(hi[0], hi[1]);
        ph[1] = __half2(hi[2], hi[3]);
        pl[0] = __half2(lo[0], lo[1]);
        pl[1] = __half2(lo[2], lo[3]);
    } else {
        int bb = b - 1024;
        wsplit_h_body(W1, Bh, IN_CH_, MP_CH, bb & 15, bb >> 4, t);
    }
}

// ---------------- HMMA fp16 2-pass GEMM: D = Ah*Bh + Al*Bh (+bias)(+relu) --------
// A split exactly into fp16 hi+lo; B rounded to fp16. err ~ A*(B-fp16(B)) ~ 2^-11.
#define H_AH 0
#define H_AL 10240
#define H_BH 20480
#define H_STAGE 30720
#define SM_TOTAL_H (2 * H_STAGE)

__global__ __launch_bounds__(256, 2) void k_mmah(
    const __half* __restrict__ Ah, const __half* __restrict__ Al,
    const __half* __restrict__ Bh, const float* __restrict__ bias,
    float* __restrict__ C, int Kdim, int Nn, int relu)
{
    extern __shared__ char smem[];
    unsigned sb = smem_u32(smem);
    int tid = threadIdx.x;
    int wid = tid >> 5, lane = tid & 31;
    int wm = wid >> 2, wn = wid & 3;

    int m0 = blockIdx.y * 128, n0 = blockIdx.x * 128;
    int nch = Kdim >> 5;

    float acc[4][4][4];
    #pragma unroll
    for (int mt = 0; mt < 4; mt++)
        #pragma unroll
        for (int nt = 0; nt < 4; nt++)
            #pragma unroll
            for (int q = 0; q < 4; q++) acc[mt][nt][q] = 0.f;

    // prologue load
    {
        #pragma unroll
        for (int it = 0; it < 2; it++) {
            int c = it * 256 + tid;
            int row = c >> 2, seg = c & 3;
            unsigned so = row * 80 + seg * 16;
            size_t goa = (size_t)(m0 + row) * Kdim + seg * 8;
            size_t gob = (size_t)(n0 + row) * Kdim + seg * 8;
            cp16(sb + H_AH + so, Ah + goa);
            cp16(sb + H_AL + so, Al + goa);
            cp16(sb + H_BH + so, Bh + gob);
        }
        cp_commit();
    }

    for (int ch = 0; ch < nch; ch++) {
        unsigned stage = sb + (unsigned)(ch & 1) * H_STAGE;
        if (ch + 1 < nch) {
            unsigned nstage = sb + (unsigned)((ch + 1) & 1) * H_STAGE;
            int k0g = (ch + 1) << 5;
            #pragma unroll
            for (int it = 0; it < 2; it++) {
                int c = it * 256 + tid;
                int row = c >> 2, seg = c & 3;
                unsigned so = row * 80 + seg * 16;
                size_t goa = (size_t)(m0 + row) * Kdim + k0g + seg * 8;
                size_t gob = (size_t)(n0 + row) * Kdim + k0g + seg * 8;
                cp16(nstage + H_AH + so, Ah + goa);
                cp16(nstage + H_AL + so, Al + goa);
                cp16(nstage + H_BH + so, Bh + gob);
            }
            cp_commit();
            cp_wait1();
        } else {
            cp_wait0();
        }
        __syncthreads();

        unsigned AsH = stage + H_AH, AsL = stage + H_AL, BsH = stage + H_BH;
        #pragma unroll
        for (int k0 = 0; k0 < 32; k0 += 16) {
            unsigned bh[4][2], ah[4][4], al[4][4];
            int rB = lane & 7, kB = lane & 8;
            #pragma unroll
            for (int nt = 0; nt < 4; nt++) {
                unsigned off = (unsigned)(wn * 32 + nt * 8 + rB) * 80 + (k0 + kB) * 2;
                ldsm2(bh[nt][0], bh[nt][1], BsH + off);
            }
            int rA = lane & 15, kA = (lane >> 4) << 3;
            #pragma unroll
            for (int mt = 0; mt < 4; mt++) {
                unsigned off = (unsigned)(wm * 64 + mt * 16 + rA) * 80 + (k0 + kA) * 2;
                ldsm4(ah[mt][0], ah[mt][1], ah[mt][2], ah[mt][3], AsH + off);
                ldsm4(al[mt][0], al[mt][1], al[mt][2], al[mt][3], AsL + off);
            }
            #pragma unroll
            for (int mt = 0; mt < 4; mt++)
                #pragma unroll
                for (int nt = 0; nt < 4; nt++) {
                    mma16816h(acc[mt][nt], ah[mt], bh[nt]);
                    mma16816h(acc[mt][nt], al[mt], bh[nt]);
                }
        }
        __syncthreads();
    }

    int tr = lane >> 2, tc = (lane & 3) << 1;
    #pragma unroll
    for (int mt = 0; mt < 4; mt++) {
        int rbase = m0 + wm * 64 + mt * 16 + tr;
        #pragma unroll
        for (int nt = 0; nt < 4; nt++) {
            int col = n0 + wn * 32 + nt * 8 + tc;
            float b0 = 0.f, b1 = 0.f;
            if (bias) { b0 = bias[col]; b1 = bias[col + 1]; }
            float v0 = acc[mt][nt][0] + b0, v1 = acc[mt][nt][1] + b1;
            float v2 = acc[mt][nt][2] + b0, v3 = acc[mt][nt][3] + b1;
            if (relu) {
                v0 = fmaxf(v0, 0.f); v1 = fmaxf(v1, 0.f);
                v2 = fmaxf(v2, 0.f); v3 = fmaxf(v3, 0.f);
            }
            *(float2*)&C[(size_t)rbase * Nn + col]       = make_float2(v0, v1);
            *(float2*)&C[(size_t)(rbase + 8) * Nn + col] = make_float2(v2, v3);
        }
    }
}

// ---------------- GTVConv aggregate + elu + fused fp16 split (warp per dst) ------
// fp32 float4 gathers; payload staging + shfl broadcast; x4 edge unroll; (128,4).
#define CONV_EDGE(vv, ss, dd)                                                     \
    {                                                                             \
        const float4* hp = (const float4*)(h + (size_t)(ss) * MP_CH);             \
        _Pragma("unroll")                                                         \
        for (int j = 0; j < 4; j++) {                                             \
            vv[j] = hp[lane + 32 * j];                                            \
            dd += fabsf(vv[j].x - hd[j].x) + fabsf(vv[j].y - hd[j].y)             \
                + fabsf(vv[j].z - hd[j].z) + fabsf(vv[j].w - hd[j].w);            \
        }                                                                         \
    }
#define CONV_ACC(vv, gg)                                                          \
    {                                                                             \
        _Pragma("unroll")                                                         \
        for (int j = 0; j < 4; j++) {                                             \
            acc[j].x = fmaf(gg, vv[j].x, acc[j].x);                               \
            acc[j].y = fmaf(gg, vv[j].y, acc[j].y);                               \
            acc[j].z = fmaf(gg, vv[j].z, acc[j].z);                               \
            acc[j].w = fmaf(gg, vv[j].w, acc[j].w);                               \
        }                                                                         \
    }

__global__ __launch_bounds__(128, 4) void k_conv(
    const float* __restrict__ h, const float* __restrict__ bias,
    __half* __restrict__ Ah, __half* __restrict__ Al)
{
    int warp = (blockIdx.x * blockDim.x + threadIdx.x) >> 5;
    int lane = threadIdx.x & 31;
    if (warp >= N_NODES) return;
    const float4* hd4 = (const float4*)(h + (size_t)warp * MP_CH);
    float4 hd[4], acc[4];
    #pragma unroll
    for (int j = 0; j < 4; j++) {
        hd[j] = hd4[lane + 32 * j];
        acc[j] = make_float4(0.f, 0.f, 0.f, 0.f);
    }
    float deg = 0.f;
    int p0 = g_rowptr[warp], p1 = g_rowptr[warp + 1];

    for (int base = p0; base < p1; base += 32) {
        int navail = p1 - base;
        if (navail > 32) navail = 32;
        int psrc = 0, pwb = 0;
        if (lane < navail) {
            int2 pp = g_epay[base + lane];
            psrc = pp.x; pwb = pp.y;
        }
        int g = 0;
        for (; g + 4 <= navail; g += 4) {
            int s0 = __shfl_sync(0xffffffffu, psrc, g + 0);
            int w0 = __shfl_sync(0xffffffffu, pwb,  g + 0);
            int s1 = __shfl_sync(0xffffffffu, psrc, g + 1);
            int w1 = __shfl_sync(0xffffffffu, pwb,  g + 1);
            int s2 = __shfl_sync(0xffffffffu, psrc, g + 2);
            int w2 = __shfl_sync(0xffffffffu, pwb,  g + 2);
            int s3 = __shfl_sync(0xffffffffu, psrc, g + 3);
            int w3 = __shfl_sync(0xffffffffu, pwb,  g + 3);
            float4 v0[4], v1[4], v2[4], v3[4];
            float d0 = 0.f, d1 = 0.f, d2 = 0.f, d3 = 0.f;
            CONV_EDGE(v0, s0, d0);
            CONV_EDGE(v1, s1, d1);
            CONV_EDGE(v2, s2, d2);
            CONV_EDGE(v3, s3, d3);
            #pragma unroll
            for (int o = 16; o > 0; o >>= 1) {
                d0 += __shfl_xor_sync(0xffffffffu, d0, o);
                d1 += __shfl_xor_sync(0xffffffffu, d1, o);
                d2 += __shfl_xor_sync(0xffffffffu, d2, o);
                d3 += __shfl_xor_sync(0xffffffffu, d3, o);
            }
            float g0 = __int_as_float(w0) / fmaxf(d0, EPSF);
            float g1 = __int_as_float(w1) / fmaxf(d1, EPSF);
            float g2 = __int_as_float(w2) / fmaxf(d2, EPSF);
            float g3 = __int_as_float(w3) / fmaxf(d3, EPSF);
            deg += (g0 + g1) + (g2 + g3);
            CONV_ACC(v0, g0);
            CONV_ACC(v1, g1);
            CONV_ACC(v2, g2);
            CONV_ACC(v3, g3);
        }
        for (; g < navail; g++) {
            int s0 = __shfl_sync(0xffffffffu, psrc, g);
            int w0 = __shfl_sync(0xffffffffu, pwb,  g);
            float4 v0[4];
            float d0 = 0.f;
            CONV_EDGE(v0, s0, d0);
            #pragma unroll
            for (int o = 16; o > 0; o >>= 1) d0 += __shfl_xor_sync(0xffffffffu, d0, o);
            float g0 = __int_as_float(w0) / fmaxf(d0, EPSF);
            deg += g0;
            CONV_ACC(v0, g0);
        }
    }

    const float4* b4 = (const float4*)bias;
    ushort4* ph = (ushort4*)(Ah + (size_t)warp * MP_CH);
    ushort4* pl = (ushort4*)(Al + (size_t)warp * MP_CH);
    #pragma unroll
    for (int j = 0; j < 4; j++) {
        float4 bb = b4[lane + 32 * j];
        float o[4];
        o[0] = hd[j].x - DELTAF * (deg * hd[j].x - acc[j].x) + bb.x;
        o[1] = hd[j].y - DELTAF * (deg * hd[j].y - acc[j].y) + bb.y;
        o[2] = hd[j].z - DELTAF * (deg * hd[j].z - acc[j].z) + bb.z;
        o[3] = hd[j].w - DELTAF * (deg * hd[j].w - acc[j].w) + bb.w;
        ushort4 uh, ul;
        unsigned short* puh = (unsigned short*)&uh;
        unsigned short* pul = (unsigned short*)&ul;
        #pragma unroll
        for (int t = 0; t < 4; t++) {
            float e = (o[t] > 0.f) ? o[t] : expm1f(o[t]);
            __half hi = __float2half_rn(e);
            __half lo = __float2half_rn(e - __half2float(hi));
            puh[t] = *(unsigned short*)&hi;
            pul[t] = *(unsigned short*)&lo;
        }
        ph[lane + 32 * j] = uh;
        pl[lane + 32 * j] = ul;
    }
}

// ---------------- s_logits = hid @ Wm2 + bm2 ; fused softmax (warp per row) ------
__global__ __launch_bounds__(256) void k_mlp2(
    const float* __restrict__ hid, const float* __restrict__ Wm2,
    const float* __restrict__ bm2, float* __restrict__ out)
{
    __shared__ float ws[HID_ * KCL];
    for (int i = threadIdx.x; i < HID_ * KCL; i += 256) ws[i] = Wm2[i];
    __syncthreads();
    int warp = threadIdx.x >> 5, lane = threadIdx.x & 31;
    int row = blockIdx.x * 8 + warp;
    if (row >= N_NODES) return;
    float acc[KCL];
    #pragma unroll
    for (int k = 0; k < KCL; k++) acc[k] = 0.f;
    const float4* h4 = (const float4*)(hid + (size_t)row * HID_);
    #pragma unroll
    for (int ii = 0; ii < 2; ii++) {
        int c4 = lane + ii * 32;
        float4 v = h4[c4];
        int cb = c4 * 4;
        #pragma unroll
        for (int k = 0; k < KCL; k++) {
            acc[k] = fmaf(v.x, ws[(cb + 0) * KCL + k],
                     fmaf(v.y, ws[(cb + 1) * KCL + k],
                     fmaf(v.z, ws[(cb + 2) * KCL + k],
                     fmaf(v.w, ws[(cb + 3) * KCL + k], acc[k]))));
        }
    }
    #pragma unroll
    for (int k = 0; k < KCL; k++) {
        #pragma unroll
        for (int o = 16; o > 0; o >>= 1) acc[k] += __shfl_xor_sync(0xffffffffu, acc[k], o);
    }
    if (lane == 0) {
        float v[KCL];
        float m = -1e30f;
        #pragma unroll
        for (int k = 0; k < KCL; k++) {
            v[k] = acc[k] + bm2[k];
            out[(size_t)row * KCL + k] = v[k];
            m = fmaxf(m, v[k]);
        }
        float sum = 0.f;
        #pragma unroll
        for (int k = 0; k < KCL; k++) { v[k] = expf(v[k] - m); sum += v[k]; }
        float inv = 1.f / sum;
        #pragma unroll
        for (int k = 0; k < KCL; k++) g_s[row * KCL + k] = v[k] * inv;
    }
}

// ---------------- fused: TV partials (256 blocks) + quant radix-select (10) -----
__global__ __launch_bounds__(1024) void k_tvquant(
    const int* __restrict__ src, const int* __restrict__ dst,
    const float* __restrict__ ew)
{
    __shared__ double shd[1024];
    __shared__ unsigned su[N_NODES];
    __shared__ unsigned hist[256];
    __shared__ unsigned sh_bsel;
    __shared__ unsigned sh_R;
    int tid = threadIdx.x;
    int b = blockIdx.x;
    if (b < 256) {
        int e = b * 1024 + tid;
        int si = src[e], di = dst[e];
        float w = ew[e];
        float sum = 0.f;
        #pragma unroll
        for (int k = 0; k < KCL; k++) sum += fabsf(g_s[si * KCL + k] - g_s[di * KCL + k]);
        double val = (double)w * (double)sum;

        unsigned key = (unsigned)si * (unsigned)N_NODES + (unsigned)di;
        unsigned m = 1u << (key & 31u);
        unsigned old = atomicOr(&g_bitmap[key >> 5], m);
        int isnew = ((old & m) == 0u) ? 1 : 0;
        unsigned bal = __ballot_sync(0xffffffffu, isnew);
        if ((tid & 31) == 0) atomicAdd(&g_nedges, __popc(bal));

        shd[tid] = val;
        __syncthreads();
        for (int o = 512; o > 0; o >>= 1) {
            if (tid < o) shd[tid] += shd[tid + o];
            __syncthreads();
        }
        if (tid == 0) g_tv_part[b] = shd[0];
    } else {
        int k = b - 256;
        for (int i = tid; i < N_NODES; i += 1024)
            su[i] = __float_as_uint(g_s[i * KCL + k]);
        if (tid == 0) sh_R = N_NODES - (N_NODES / KCL + 1);   // 7372
        unsigned mask = 0, val = 0;
        #pragma unroll
        for (int r = 0; r < 4; r++) {
            int shift = 24 - 8 * r;
            if (tid < 256) hist[tid] = 0;
            __syncthreads();
            for (int i = tid; i < N_NODES; i += 1024) {
                unsigned u = su[i];
                if ((u & mask) == val) atomicAdd(&hist[(u >> shift) & 255u], 1u);
            }
            __syncthreads();
            if (tid == 0) {
                unsigned R = sh_R, cum = 0, bsel = 255;
                for (int bin = 0; bin < 256; bin++) {
                    unsigned c = hist[bin];
                    if (R < cum + c) { bsel = bin; break; }
                    cum += c;
                }
                sh_bsel = bsel;
                sh_R = R - cum;
            }
            __syncthreads();
            val |= sh_bsel << shift;
            mask |= 0xFFu << shift;
        }
        if (tid == 0) g_quant[k] = __uint_as_float(val);
    }
}

// ---------------- fused: asym partials + final reduction + state clears ----------
__global__ __launch_bounds__(1024) void k_asymfinal(float* __restrict__ out) {
    __shared__ double sh[1024];
    __shared__ int lastflag;
    int tid = threadIdx.x;
    int i = blockIdx.x * 1024 + tid;   // 80 * 1024 = 81920 exact
    float q = g_quant[i % KCL];
    float t = g_s[i] - q;
    double v = (t >= 0.f) ? (double)((KCL - 1) * t) : (double)(-t);
    sh[tid] = v;
    __syncthreads();
    for (int o = 512; o > 0; o >>= 1) {
        if (tid < o) sh[tid] += sh[tid + o];
        __syncthreads();
    }
    if (tid == 0) {
        g_asym_part[blockIdx.x] = sh[0];
        __threadfence();
        lastflag = (atomicAdd(&g_done, 1) == 79) ? 1 : 0;
    }
    __syncthreads();
    if (lastflag) {
        sh[tid] = (tid < 256) ? g_tv_part[tid] : 0.0;
        __syncthreads();
        for (int o = 512; o > 0; o >>= 1) {
            if (tid < o) sh[tid] += sh[tid + o];
            __syncthreads();
        }
        double tvsum = sh[0];
        __syncthreads();
        sh[tid] = (tid < 80) ? g_asym_part[tid] : 0.0;
        __syncthreads();
        for (int o = 512; o > 0; o >>= 1) {
            if (tid < o) sh[tid] += sh[tid + o];
            __syncthreads();
        }
        if (tid == 0) {
            double asum = sh[0];
            double tv = tvsum / (2.0 * (double)g_nedges);
            double denom = (double)N_NODES * (double)(KCL - 1);
            double balv = (denom - asum) / denom;
            out[N_NODES * KCL + 0] = (float)((double)TV_COEFF * tv);
            out[N_NODES * KCL + 1] = (float)((double)BAL_COEFF * balv);
            g_nedges = 0;
            g_done = 0;
        }
        for (int c = tid; c < N_NODES; c += 1024) g_counts[c] = 0;
    }
}

// ---------------- launch ----------------
extern "C" void kernel_launch(void* const* d_in, const int* in_sizes, int n_in,
                              void* d_out, int out_size) {
    const float* x   = (const float*)d_in[0];
    const int*   ei  = (const int*)d_in[1];
    const float* ew  = (const float*)d_in[2];
    const float* W1  = (const float*)d_in[3];
    const float* b1  = (const float*)d_in[4];
    const float* W2  = (const float*)d_in[5];
    const float* b2  = (const float*)d_in[6];
    const float* Wm1 = (const float*)d_in[7];
    const float* bm1 = (const float*)d_in[8];
    const float* Wm2 = (const float*)d_in[9];
    const float* bm2 = (const float*)d_in[10];
    const int* src = ei;
    const int* dst = ei + E_EDGES;
    float* out = (float*)d_out;

    float *pA, *pHid;
    __half *pAh, *pAl, *pBh1, *pBh2, *pBh3;
    cudaGetSymbolAddress((void**)&pA,   g_bufA);
    cudaGetSymbolAddress((void**)&pHid, g_hid);
    cudaGetSymbolAddress((void**)&pAh,  g_ah);
    cudaGetSymbolAddress((void**)&pAl,  g_al);
    cudaGetSymbolAddress((void**)&pBh1, g_bh1);
    cudaGetSymbolAddress((void**)&pBh2, g_bh2);
    cudaGetSymbolAddress((void**)&pBh3, g_bh3);

    cudaFuncSetAttribute(k_mmah, cudaFuncAttributeMaxDynamicSharedMemorySize, SM_TOTAL_H);

    static cudaStream_t s2 = nullptr;
    static cudaEvent_t evF = nullptr, ev1 = nullptr, ev2 = nullptr, ev3 = nullptr;
    if (!s2) {
        cudaStreamCreate(&s2);
        cudaEventCreateWithFlags(&evF, cudaEventDisableTiming);
        cudaEventCreateWithFlags(&ev1, cudaEventDisableTiming);
        cudaEventCreateWithFlags(&ev2, cudaEventDisableTiming);
        cudaEventCreateWithFlags(&ev3, cudaEventDisableTiming);
    }

    // submission order: #4 = mma1 (profiler window -> fp16 GEMM validation)
    cudaEventRecord(evF, 0);
    cudaStreamWaitEvent(s2, evF, 0);
    k_hist<<<E_EDGES / 1024, 256, 0, s2>>>(src, dst);          // #1
    k_scan<<<1, 1024, 0, s2>>>();                              // #2
    k_fsplit<<<1024 + 64, 256>>>(x, W1, pAh, pAl, pBh1);       // #3 (main)
    k_mmah<<<dim3(MP_CH / 128, N_NODES / 128), 256, SM_TOTAL_H>>>(
        pAh, pAl, pBh1, nullptr, pA, IN_CH_, MP_CH, 0);        // #4
    k_scatter<<<E_EDGES / 1024, 256, 0, s2>>>(src, dst, ew);   // #5 (overlaps mma1)
    cudaEventRecord(ev1, s2);
    cudaStreamWaitEvent(0, ev1, 0);
    k_conv<<<N_NODES / 4, 128>>>(pA, b1, pAh, pAl);            // #6

    k_wsplit_h<<<dim3(MP_CH / 32, MP_CH / 32), 256, 0, s2>>>(W2, pBh2, MP_CH, MP_CH);  // #7
    cudaEventRecord(ev2, s2);
    k_wsplit_h<<<dim3(HID_ / 32, MP_CH / 32), 256, 0, s2>>>(Wm1, pBh3, MP_CH, HID_);   // #8
    cudaEventRecord(ev3, s2);

    cudaStreamWaitEvent(0, ev2, 0);
    k_mmah<<<dim3(MP_CH / 128, N_NODES / 128), 256, SM_TOTAL_H>>>(
        pAh, pAl, pBh2, nullptr, pA, MP_CH, MP_CH, 0);         // #9
    k_conv<<<N_NODES / 4, 128>>>(pA, b2, pAh, pAl);            // #10

    cudaStreamWaitEvent(0, ev3, 0);
    k_mmah<<<dim3(HID_ / 128, N_NODES / 128), 256, SM_TOTAL_H>>>(
        pAh, pAl, pBh3, bm1, pHid, MP_CH, HID_, 1);            // #11
    k_mlp2<<<N_NODES / 8, 256>>>(pHid, Wm2, bm2, out);         // #12

    k_tvquant<<<256 + KCL, 1024>>>(src, dst, ew);              // #13
    k_asymfinal<<<(N_NODES * KCL) / 1024, 1024>>>(out);        // #14
}